// round 13
// baseline (speedup 1.0000x reference)
#include <cuda_runtime.h>
#include <cuda_bf16.h>
#include <cuda_fp16.h>
#include <cstdint>

#define NN 50000
#define HH 128
#define CC 16
#define RR 8
#define BB 4
#define EE 800000

// ---------------- scratch (device globals; no allocations) ----------------
__device__ float g_x0[(size_t)NN * HH];              // layer0 out (pre-relu)
__device__ float g_x1[(size_t)NN * HH];              // layer1 out (pre-relu)
__device__ __half g_t0[(size_t)RR * NN * HH];        // composed layer0 tables (102.4 MB)
__device__ __half g_t1[(size_t)RR * NN * HH];        // composed layer1 tables (102.4 MB)
__device__ __half g_t2[(size_t)RR * NN * CC];        // composed layer2 tables (12.8 MB)
__device__ __half g_y1h[(size_t)4 * NN * HH];        // layer1 basis products, fp16
__device__ float g_z2[(size_t)4 * NN * CC];          // layer2 basis products, fp32
__device__ __nv_bfloat16 g_w1thi[5 * 128 * 128];     // bf16 hi image (slice 4 = loop1^T used)
__device__ __nv_bfloat16 g_w1tlo[5 * 128 * 128];     // bf16 lo residual
__device__ __half g_w1tf[4 * 128 * 128];             // fp16 image, slices 0..3 (bases1^T)

// ---------------- helpers ----------------
__device__ __forceinline__ void redAdd4(float* p, float4 v) {
    asm volatile("red.global.add.v4.f32 [%0], {%1, %2, %3, %4};"
                 :: "l"(__cvta_generic_to_global(p)), "f"(v.x), "f"(v.y), "f"(v.z), "f"(v.w)
                 : "memory");
}
__device__ __forceinline__ uint32_t pack_bf16(float a, float b) {
    __nv_bfloat162 t = __floats2bfloat162_rn(a, b);
    return *(uint32_t*)&t;
}
__device__ __forceinline__ uint32_t pack_f16(float a, float b) {
    __half2 t = __floats2half2_rn(a, b);
    return *(uint32_t*)&t;
}
__device__ __forceinline__ uint32_t smem_u32(const void* p) {
    uint32_t a;
    asm("{ .reg .u64 t; cvta.to.shared.u64 t, %1; cvt.u32.u64 %0, t; }" : "=r"(a) : "l"(p));
    return a;
}
#define MMA16816BF(c, a0, a1, a2, a3, b0, b1)                                 \
    asm volatile("mma.sync.aligned.m16n8k16.row.col.f32.bf16.bf16.f32 "       \
                 "{%0,%1,%2,%3}, {%4,%5,%6,%7}, {%8,%9}, {%0,%1,%2,%3};"      \
                 : "+f"((c)[0]), "+f"((c)[1]), "+f"((c)[2]), "+f"((c)[3])     \
                 : "r"(a0), "r"(a1), "r"(a2), "r"(a3), "r"(b0), "r"(b1))
#define MMA16816F(c, a0, a1, a2, a3, b0, b1)                                  \
    asm volatile("mma.sync.aligned.m16n8k16.row.col.f32.f16.f16.f32 "         \
                 "{%0,%1,%2,%3}, {%4,%5,%6,%7}, {%8,%9}, {%0,%1,%2,%3};"      \
                 : "+f"((c)[0]), "+f"((c)[1]), "+f"((c)[2]), "+f"((c)[3])     \
                 : "r"(a0), "r"(a1), "r"(a2), "r"(a3), "r"(b0), "r"(b1))
#define LDSM4(r, addr)                                                        \
    asm volatile("ldmatrix.sync.aligned.m8n8.x4.shared.b16 {%0,%1,%2,%3}, [%4];" \
                 : "=r"((r)[0]), "=r"((r)[1]), "=r"((r)[2]), "=r"((r)[3])     \
                 : "r"(addr))

// smem geometry: 16-bit rows, stride 136 elems (272 B)
#define LSTRIDE 136
#define AH_OFF 0
#define AL_OFF 17408
#define WH_OFF 34816
#define WL_OFF 69632
#define SMEM_X1 104448
#define FA_OFF 0
#define FW_OFF 17408
#define SMEM_F16 52224

// ---------------- prep: weight images ----------------
__global__ void prep_w1t(const float* __restrict__ bases1, const float* __restrict__ loop1,
                         __nv_bfloat16* __restrict__ whi, __nv_bfloat16* __restrict__ wlo,
                         __half* __restrict__ wf) {
    int i = blockIdx.x * 256 + threadIdx.x;
    if (i >= 5 * 16384) return;
    int s = i >> 14;
    int f = (i >> 7) & 127;
    int d = i & 127;
    float v = (s < 4) ? __ldg(&bases1[s * 16384 + d * 128 + f]) : __ldg(&loop1[d * 128 + f]);
    __nv_bfloat16 hi = __float2bfloat16(v);
    __nv_bfloat16 lo = __float2bfloat16(v - __bfloat162float(hi));
    whi[i] = hi;
    wlo[i] = lo;
    if (s < 4) wf[i] = __float2half(v);
}

// ---------------- compose0: T0[r][n][:] = sum_b wcomp0[r,b] * bases0[b][n][:]  (fp32 in, fp16 out) ----------------
__global__ void compose0_k(const float* __restrict__ b0, const float* __restrict__ wc,
                           __half* __restrict__ T0) {
    int i = blockIdx.x * 256 + threadIdx.x;      // over NN*32 float4-groups
    if (i >= NN * 32) return;
    const float4* bp = (const float4*)b0;
    const long PS = (long)NN * 32;
    float4 v0 = __ldg(bp + i);
    float4 v1 = __ldg(bp + i + PS);
    float4 v2 = __ldg(bp + i + 2 * PS);
    float4 v3 = __ldg(bp + i + 3 * PS);
    uint2* tp = (uint2*)T0;
#pragma unroll
    for (int r = 0; r < RR; r++) {
        float c0 = __ldg(&wc[r * 4 + 0]), c1 = __ldg(&wc[r * 4 + 1]);
        float c2 = __ldg(&wc[r * 4 + 2]), c3 = __ldg(&wc[r * 4 + 3]);
        float mx = c0 * v0.x + c1 * v1.x + c2 * v2.x + c3 * v3.x;
        float my = c0 * v0.y + c1 * v1.y + c2 * v2.y + c3 * v3.y;
        float mz = c0 * v0.z + c1 * v1.z + c2 * v2.z + c3 * v3.z;
        float mw = c0 * v0.w + c1 * v1.w + c2 * v2.w + c3 * v3.w;
        uint2 u = { pack_f16(mx, my), pack_f16(mz, mw) };
        tp[(size_t)r * PS + i] = u;
    }
}

// ---------------- compose1: T1[r][n][:] = sum_b wcomp1[r,b] * Y_b[n][:]  (fp16 in, fp16 out) ----------------
__global__ void compose1_k(const __half* __restrict__ Yh, const float* __restrict__ wc,
                           __half* __restrict__ T1) {
    int i = blockIdx.x * 256 + threadIdx.x;      // over NN*32 uint2-groups
    if (i >= NN * 32) return;
    const uint2* yp = (const uint2*)Yh;
    const long PS = (long)NN * 32;
    uint2 u0 = __ldg(yp + i);
    uint2 u1 = __ldg(yp + i + PS);
    uint2 u2 = __ldg(yp + i + 2 * PS);
    uint2 u3 = __ldg(yp + i + 3 * PS);
    float2 a0 = __half22float2(*(const __half2*)&u0.x), b0 = __half22float2(*(const __half2*)&u0.y);
    float2 a1 = __half22float2(*(const __half2*)&u1.x), b1 = __half22float2(*(const __half2*)&u1.y);
    float2 a2 = __half22float2(*(const __half2*)&u2.x), b2 = __half22float2(*(const __half2*)&u2.y);
    float2 a3 = __half22float2(*(const __half2*)&u3.x), b3 = __half22float2(*(const __half2*)&u3.y);
    uint2* tp = (uint2*)T1;
#pragma unroll
    for (int r = 0; r < RR; r++) {
        float c0 = __ldg(&wc[r * 4 + 0]), c1 = __ldg(&wc[r * 4 + 1]);
        float c2 = __ldg(&wc[r * 4 + 2]), c3 = __ldg(&wc[r * 4 + 3]);
        float mx = c0 * a0.x + c1 * a1.x + c2 * a2.x + c3 * a3.x;
        float my = c0 * a0.y + c1 * a1.y + c2 * a2.y + c3 * a3.y;
        float mz = c0 * b0.x + c1 * b1.x + c2 * b2.x + c3 * b3.x;
        float mw = c0 * b0.y + c1 * b1.y + c2 * b2.y + c3 * b3.y;
        uint2 u = { pack_f16(mx, my), pack_f16(mz, mw) };
        tp[(size_t)r * PS + i] = u;
    }
}

// ---------------- compose2: T2[r][n][:] = sum_b wcomp2[r,b] * Z_b[n][:]  (fp32 in, fp16 out) ----------------
__global__ void compose2_k(const float* __restrict__ Z, const float* __restrict__ wc,
                           __half* __restrict__ T2) {
    int i = blockIdx.x * 256 + threadIdx.x;      // over NN*4 float4-groups
    if (i >= NN * 4) return;
    const float4* zp = (const float4*)Z;
    const long PS = (long)NN * 4;
    float4 v0 = __ldg(zp + i);
    float4 v1 = __ldg(zp + i + PS);
    float4 v2 = __ldg(zp + i + 2 * PS);
    float4 v3 = __ldg(zp + i + 3 * PS);
    uint2* tp = (uint2*)T2;
#pragma unroll
    for (int r = 0; r < RR; r++) {
        float c0 = __ldg(&wc[r * 4 + 0]), c1 = __ldg(&wc[r * 4 + 1]);
        float c2 = __ldg(&wc[r * 4 + 2]), c3 = __ldg(&wc[r * 4 + 3]);
        float mx = c0 * v0.x + c1 * v1.x + c2 * v2.x + c3 * v3.x;
        float my = c0 * v0.y + c1 * v1.y + c2 * v2.y + c3 * v3.y;
        float mz = c0 * v0.z + c1 * v1.z + c2 * v2.z + c3 * v3.z;
        float mw = c0 * v0.w + c1 * v1.w + c2 * v2.w + c3 * v3.w;
        uint2 u = { pack_f16(mx, my), pack_f16(mz, mw) };
        tp[(size_t)r * PS + i] = u;
    }
}

// ---------------- layer 0 init: x0 = loop0[h] + bias0 ----------------
__global__ void init0_k(const int* __restrict__ h, const float* __restrict__ loop0,
                        const float* __restrict__ bias0, float* __restrict__ out) {
    int i = blockIdx.x * 256 + threadIdx.x;
    if (i >= NN * HH) return;
    int n = i >> 7;
    int f = i & 127;
    int id = __ldg(&h[n]);
    out[i] = __ldg(&loop0[(size_t)id * HH + f]) + __ldg(&bias0[f]);
}

// ---------------- scatter (H=128): one warp per edge, single composed-row gather ----------------
// T row index: via node-id table (h) for layer 0, identity for layer 1.
__global__ void __launch_bounds__(256) scatterH_k(
    const int* __restrict__ src, const int* __restrict__ dst, const int* __restrict__ h,
    const int* __restrict__ rel, const float* __restrict__ norm,
    const __half* __restrict__ T, float* __restrict__ out) {
    int e = (blockIdx.x * 256 + threadIdx.x) >> 5;
    if (e >= EE) return;
    int lane = threadIdx.x & 31;
    int s = __ldg(&src[e]);
    int d = __ldg(&dst[e]);
    int rr = __ldg(&rel[e]);
    float nm = __ldg(&norm[e]);
    int sid = h ? __ldg(&h[s]) : s;
    const uint2* tp = (const uint2*)T + ((size_t)rr * NN + sid) * 32 + lane;
    uint2 u = __ldg(tp);
    float2 a = __half22float2(*(const __half2*)&u.x);
    float2 b = __half22float2(*(const __half2*)&u.y);
    float4 m = { a.x * nm, a.y * nm, b.x * nm, b.y * nm };
    redAdd4(out + (long)d * HH + lane * 4, m);
}

// ---------------- layer 2 scatter: 4 lanes per edge, single composed-row gather ----------------
__global__ void __launch_bounds__(256) scatter2_k(
    const int* __restrict__ src, const int* __restrict__ dst, const int* __restrict__ rel,
    const float* __restrict__ norm, const __half* __restrict__ T2,
    float* __restrict__ out) {
    int tid = blockIdx.x * 256 + threadIdx.x;
    int e = tid >> 2;
    if (e >= EE) return;
    int q = tid & 3;
    int s = __ldg(&src[e]);
    int d = __ldg(&dst[e]);
    int rr = __ldg(&rel[e]);
    float nm = __ldg(&norm[e]);
    const uint2* tp = (const uint2*)T2 + ((size_t)rr * NN + s) * 4 + q;
    uint2 u = __ldg(tp);
    float2 a = __half22float2(*(const __half2*)&u.x);
    float2 b = __half22float2(*(const __half2*)&u.y);
    float4 m = { a.x * nm, a.y * nm, b.x * nm, b.y * nm };
    redAdd4(out + (long)d * CC + q * 4, m);
}

// ---------------- fp16 HMMA transform: Y_b = relu(x0) @ B1_b  (slices 0..3) ----------------
__global__ void __launch_bounds__(256, 3) mma_f16(
    const float* __restrict__ X, const __half* __restrict__ Wf,
    __half* __restrict__ Yh) {
    extern __shared__ char sm[];
    const int tid = threadIdx.x;
    const int w = tid >> 5;
    const int lane = tid & 31;
    const int slice = blockIdx.y;
    const int row0 = blockIdx.x * 64;

    {
        const uint2* g = (const uint2*)(Wf + slice * 16384);
#pragma unroll
        for (int i = 0; i < 16; i++) {
            int r = w * 16 + i;
            uint2 v = __ldg(g + r * 32 + lane);
            *(uint2*)(sm + FW_OFF + r * (LSTRIDE * 2) + lane * 8) = v;
        }
    }
    {
#pragma unroll
        for (int i = 0; i < 8; i++) {
            int r = w * 8 + i;
            int rg = row0 + r;
            float4 q = (rg < NN) ? __ldg((const float4*)X + (long)rg * 32 + lane)
                                 : make_float4(0.f, 0.f, 0.f, 0.f);
            uint2 u = { pack_f16(fmaxf(q.x, 0.f), fmaxf(q.y, 0.f)),
                        pack_f16(fmaxf(q.z, 0.f), fmaxf(q.w, 0.f)) };
            *(uint2*)(sm + FA_OFF + r * (LSTRIDE * 2) + lane * 8) = u;
        }
    }
    __syncthreads();

    const int wm = w & 1, wn = w >> 1;
    const int r0 = wm * 32, c0 = wn * 32;
    const uint32_t lrow = lane & 15;
    const uint32_t lkh = (lane >> 4) << 3;
    const uint32_t sA = smem_u32(sm + FA_OFF), sW = smem_u32(sm + FW_OFF);

    float acc[2][4][4];
#pragma unroll
    for (int mi = 0; mi < 2; mi++)
#pragma unroll
        for (int j = 0; j < 4; j++)
            acc[mi][j][0] = acc[mi][j][1] = acc[mi][j][2] = acc[mi][j][3] = 0.f;

#pragma unroll
    for (int ks = 0; ks < 8; ks++) {
        const uint32_t kb = ks * 16 + lkh;
        uint32_t A[2][4], B[2][4];
#pragma unroll
        for (int mi = 0; mi < 2; mi++)
            LDSM4(A[mi], sA + ((r0 + mi * 16 + lrow) * LSTRIDE + kb) * 2);
#pragma unroll
        for (int nj = 0; nj < 2; nj++)
            LDSM4(B[nj], sW + ((c0 + nj * 16 + lrow) * LSTRIDE + kb) * 2);
#pragma unroll
        for (int mi = 0; mi < 2; mi++)
#pragma unroll
            for (int nj = 0; nj < 2; nj++) {
                MMA16816F(acc[mi][nj * 2],     A[mi][0], A[mi][1], A[mi][2], A[mi][3], B[nj][0], B[nj][2]);
                MMA16816F(acc[mi][nj * 2 + 1], A[mi][0], A[mi][1], A[mi][2], A[mi][3], B[nj][1], B[nj][3]);
            }
    }

    __half* O = Yh + (size_t)slice * NN * HH;
    const int g = lane >> 2, tg = lane & 3;
#pragma unroll
    for (int mi = 0; mi < 2; mi++) {
        long ra = row0 + r0 + mi * 16 + g;
        long rb = ra + 8;
#pragma unroll
        for (int j = 0; j < 4; j++) {
            int col = c0 + j * 8 + tg * 2;
            if (ra < NN) *(uint32_t*)(O + ra * 128 + col) = pack_f16(acc[mi][j][0], acc[mi][j][1]);
            if (rb < NN) *(uint32_t*)(O + rb * 128 + col) = pack_f16(acc[mi][j][2], acc[mi][j][3]);
        }
    }
}

// ---------------- bf16 hi/lo HMMA: x1 = relu(x0) @ loop1 + bias1 (accurate path) ----------------
__global__ void __launch_bounds__(256, 2) mma_x1(
    const float* __restrict__ X,
    const __nv_bfloat16* __restrict__ Wth, const __nv_bfloat16* __restrict__ Wtl,
    float* __restrict__ x1, const float* __restrict__ bias1) {
    extern __shared__ char sm[];
    const int tid = threadIdx.x;
    const int w = tid >> 5;
    const int lane = tid & 31;
    const int row0 = blockIdx.x * 64;

    {
        const uint2* gh = (const uint2*)(Wth + 4 * 16384);
        const uint2* gl = (const uint2*)(Wtl + 4 * 16384);
#pragma unroll
        for (int i = 0; i < 16; i++) {
            int r = w * 16 + i;
            uint2 vh = __ldg(gh + r * 32 + lane);
            uint2 vl = __ldg(gl + r * 32 + lane);
            *(uint2*)(sm + WH_OFF + r * (LSTRIDE * 2) + lane * 8) = vh;
            *(uint2*)(sm + WL_OFF + r * (LSTRIDE * 2) + lane * 8) = vl;
        }
    }
    {
#pragma unroll
        for (int i = 0; i < 8; i++) {
            int r = w * 8 + i;
            int rg = row0 + r;
            float4 q = (rg < NN) ? __ldg((const float4*)X + (long)rg * 32 + lane)
                                 : make_float4(0.f, 0.f, 0.f, 0.f);
            q.x = fmaxf(q.x, 0.f); q.y = fmaxf(q.y, 0.f);
            q.z = fmaxf(q.z, 0.f); q.w = fmaxf(q.w, 0.f);
            float hx = __bfloat162float(__float2bfloat16(q.x));
            float hy = __bfloat162float(__float2bfloat16(q.y));
            float hz = __bfloat162float(__float2bfloat16(q.z));
            float hw = __bfloat162float(__float2bfloat16(q.w));
            uint2 uh = { pack_bf16(q.x, q.y), pack_bf16(q.z, q.w) };
            uint2 ul = { pack_bf16(q.x - hx, q.y - hy), pack_bf16(q.z - hz, q.w - hw) };
            *(uint2*)(sm + AH_OFF + r * (LSTRIDE * 2) + lane * 8) = uh;
            *(uint2*)(sm + AL_OFF + r * (LSTRIDE * 2) + lane * 8) = ul;
        }
    }
    __syncthreads();

    const int wm = w & 1, wn = w >> 1;
    const int r0 = wm * 32, c0 = wn * 32;
    const uint32_t lrow = lane & 15;
    const uint32_t lkh = (lane >> 4) << 3;
    const uint32_t sAH = smem_u32(sm + AH_OFF), sAL = smem_u32(sm + AL_OFF);
    const uint32_t sWH = smem_u32(sm + WH_OFF), sWL = smem_u32(sm + WL_OFF);

    float acc[2][4][4];
#pragma unroll
    for (int mi = 0; mi < 2; mi++)
#pragma unroll
        for (int j = 0; j < 4; j++)
            acc[mi][j][0] = acc[mi][j][1] = acc[mi][j][2] = acc[mi][j][3] = 0.f;

#pragma unroll
    for (int ks = 0; ks < 8; ks++) {
        const uint32_t kb = ks * 16 + lkh;
        uint32_t AH[2][4], AL[2][4], BH[2][4], BL[2][4];
#pragma unroll
        for (int mi = 0; mi < 2; mi++) {
            uint32_t off = ((r0 + mi * 16 + lrow) * LSTRIDE + kb) * 2;
            LDSM4(AH[mi], sAH + off);
            LDSM4(AL[mi], sAL + off);
        }
#pragma unroll
        for (int nj = 0; nj < 2; nj++) {
            uint32_t off = ((c0 + nj * 16 + lrow) * LSTRIDE + kb) * 2;
            LDSM4(BH[nj], sWH + off);
            LDSM4(BL[nj], sWL + off);
        }
#pragma unroll
        for (int mi = 0; mi < 2; mi++)
#pragma unroll
            for (int nj = 0; nj < 2; nj++) {
                float* cA = acc[mi][nj * 2];
                float* cB = acc[mi][nj * 2 + 1];
                MMA16816BF(cA, AH[mi][0], AH[mi][1], AH[mi][2], AH[mi][3], BH[nj][0], BH[nj][2]);
                MMA16816BF(cA, AH[mi][0], AH[mi][1], AH[mi][2], AH[mi][3], BL[nj][0], BL[nj][2]);
                MMA16816BF(cA, AL[mi][0], AL[mi][1], AL[mi][2], AL[mi][3], BH[nj][0], BH[nj][2]);
                MMA16816BF(cB, AH[mi][0], AH[mi][1], AH[mi][2], AH[mi][3], BH[nj][1], BH[nj][3]);
                MMA16816BF(cB, AH[mi][0], AH[mi][1], AH[mi][2], AH[mi][3], BL[nj][1], BL[nj][3]);
                MMA16816BF(cB, AL[mi][0], AL[mi][1], AL[mi][2], AL[mi][3], BH[nj][1], BH[nj][3]);
            }
    }

    const int g = lane >> 2, tg = lane & 3;
#pragma unroll
    for (int mi = 0; mi < 2; mi++) {
        long ra = row0 + r0 + mi * 16 + g;
        long rb = ra + 8;
#pragma unroll
        for (int j = 0; j < 4; j++) {
            int col = c0 + j * 8 + tg * 2;
            float b0 = __ldg(&bias1[col]), b1 = __ldg(&bias1[col + 1]);
            if (ra < NN) {
                float2 v = { acc[mi][j][0] + b0, acc[mi][j][1] + b1 };
                *(float2*)(x1 + ra * 128 + col) = v;
            }
            if (rb < NN) {
                float2 v = { acc[mi][j][2] + b0, acc[mi][j][3] + b1 };
                *(float2*)(x1 + rb * 128 + col) = v;
            }
        }
    }
}

// ---------------- layer 2 transform, F=16: grid.y = 5 (4 bases -> Z, slot 4 -> out+bias) ----------------
__global__ void __launch_bounds__(128) transform16(
    const float* __restrict__ X, const float* __restrict__ bases2,
    const float* __restrict__ loop2, const float* __restrict__ bias2,
    float* __restrict__ Z, float* __restrict__ out) {
    __shared__ float ws[128 * 16];
    __shared__ float xs[64][129];
    const int y = blockIdx.y;
    const float* W = (y < 4) ? (bases2 + y * 2048) : loop2;
    float* O = (y < 4) ? (Z + (long)y * NN * CC) : out;
    const int t = threadIdx.x;
    const int col = t & 15, rg = t >> 4;
    const int row0 = blockIdx.x * 64;
    for (int i = t; i < 128 * 16; i += 128) ws[i] = __ldg(&W[i]);
#pragma unroll 4
    for (int i = 0; i < 64; i++) {
        int rr = row0 + i;
        float v = (rr < NN) ? __ldg(&X[(long)rr * 128 + t]) : 0.f;
        xs[i][t] = fmaxf(v, 0.f);   // relu(x1) fused
    }
    __syncthreads();
    const float bv = (y == 4) ? __ldg(&bias2[col]) : 0.f;
    for (int p = 0; p < 8; p++) {
        int rl = p * 8 + rg;
        float a = 0.f;
#pragma unroll 16
        for (int d = 0; d < 128; d++) a = fmaf(xs[rl][d], ws[d * 16 + col], a);
        int rr = row0 + rl;
        if (rr < NN) O[(long)rr * 16 + col] = a + bv;
    }
}

// ---------------- launch ----------------
extern "C" void kernel_launch(void* const* d_in, const int* in_sizes, int n_in,
                              void* d_out, int out_size) {
    const int*   src    = (const int*)d_in[0];
    const int*   dst    = (const int*)d_in[1];
    const int*   h      = (const int*)d_in[2];
    const int*   rtab   = (const int*)d_in[3];
    const float* norm   = (const float*)d_in[4];
    const float* bases0 = (const float*)d_in[5];
    const float* wcomp0 = (const float*)d_in[6];
    const float* loop0  = (const float*)d_in[7];
    const float* bias0  = (const float*)d_in[8];
    const float* bases1 = (const float*)d_in[9];
    const float* wcomp1 = (const float*)d_in[10];
    const float* loop1  = (const float*)d_in[11];
    const float* bias1  = (const float*)d_in[12];
    const float* bases2 = (const float*)d_in[13];
    const float* wcomp2 = (const float*)d_in[14];
    const float* loop2  = (const float*)d_in[15];
    const float* bias2  = (const float*)d_in[16];
    float* out = (float*)d_out;

    float *p_x0, *p_x1, *p_z2;
    __half *p_t0, *p_t1, *p_t2, *p_y1h, *p_wf;
    __nv_bfloat16 *p_whi, *p_wlo;
    cudaGetSymbolAddress((void**)&p_x0, g_x0);
    cudaGetSymbolAddress((void**)&p_x1, g_x1);
    cudaGetSymbolAddress((void**)&p_t0, g_t0);
    cudaGetSymbolAddress((void**)&p_t1, g_t1);
    cudaGetSymbolAddress((void**)&p_t2, g_t2);
    cudaGetSymbolAddress((void**)&p_y1h, g_y1h);
    cudaGetSymbolAddress((void**)&p_z2, g_z2);
    cudaGetSymbolAddress((void**)&p_whi, g_w1thi);
    cudaGetSymbolAddress((void**)&p_wlo, g_w1tlo);
    cudaGetSymbolAddress((void**)&p_wf, g_w1tf);

    static int attr_done = 0;
    if (!attr_done) {
        cudaFuncSetAttribute(mma_x1, cudaFuncAttributeMaxDynamicSharedMemorySize, SMEM_X1);
        cudaFuncSetAttribute(mma_f16, cudaFuncAttributeMaxDynamicSharedMemorySize, SMEM_F16);
        attr_done = 1;
    }

    const int nh_blocks = (NN * HH + 255) / 256;
    const int edge_warp = (EE * 32 + 255) / 256;
    const int row_t64  = (NN + 63) / 64;     // 782
    const int ncvt     = (NN * 32 + 255) / 256;

    // prep
    prep_w1t<<<(5 * 16384 + 255) / 256, 256>>>(bases1, loop1, p_whi, p_wlo, p_wf);
    compose0_k<<<ncvt, 256>>>(bases0, wcomp0, p_t0);

    // ---- layer 0 ----
    init0_k<<<nh_blocks, 256>>>(h, loop0, bias0, p_x0);
    scatterH_k<<<edge_warp, 256>>>(src, dst, h, rtab, norm, p_t0, p_x0);

    // ---- layer 1 ----
    mma_f16<<<dim3(row_t64, 4), 256, SMEM_F16>>>(p_x0, p_wf, p_y1h);
    mma_x1<<<row_t64, 256, SMEM_X1>>>(p_x0, p_whi, p_wlo, p_x1, bias1);
    compose1_k<<<ncvt, 256>>>(p_y1h, wcomp1, p_t1);
    scatterH_k<<<edge_warp, 256>>>(src, dst, nullptr, rtab, norm, p_t1, p_x1);

    // ---- layer 2 ----
    transform16<<<dim3(row_t64, 5), 128>>>(p_x1, bases2, loop2, bias2, p_z2, out);
    compose2_k<<<(NN * 4 + 255) / 256, 256>>>(p_z2, wcomp2, p_t2);
    scatter2_k<<<(EE * 4 + 255) / 256, 256>>>(src, dst, rtab, norm, p_t2, out);
}

// round 14
// speedup vs baseline: 1.2024x; 1.2024x over previous
#include <cuda_runtime.h>
#include <cuda_bf16.h>
#include <cuda_fp16.h>
#include <cstdint>

#define NN 50000
#define HH 128
#define CC 16
#define RR 8
#define BB 4
#define EE 800000

// ---------------- scratch (device globals; no allocations) ----------------
__device__ float g_x0[(size_t)NN * HH];
__device__ float g_x1[(size_t)NN * HH];
__device__ __half g_t0[(size_t)RR * NN * HH];        // composed layer0 tables (102.4 MB)
__device__ __half g_t1[(size_t)RR * NN * HH];        // composed layer1 tables (102.4 MB)
__device__ __half g_t2[(size_t)RR * NN * CC];        // composed layer2 tables (12.8 MB)
__device__ __half g_y1h[(size_t)4 * NN * HH];
__device__ float g_z2[(size_t)4 * NN * CC];
__device__ __nv_bfloat16 g_w1thi[5 * 128 * 128];
__device__ __nv_bfloat16 g_w1tlo[5 * 128 * 128];
__device__ __half g_w1tf[4 * 128 * 128];
// CSR (built once per call)
__device__ int g_deg[NN];
__device__ int g_cur[NN];
__device__ int g_off[NN + 1];
__device__ int g_trow0[EE];                          // r*NN + h[src]
__device__ int g_trow1[EE];                          // r*NN + src
__device__ float g_enorm[EE];

// ---------------- helpers ----------------
__device__ __forceinline__ uint32_t pack_bf16(float a, float b) {
    __nv_bfloat162 t = __floats2bfloat162_rn(a, b);
    return *(uint32_t*)&t;
}
__device__ __forceinline__ uint32_t pack_f16(float a, float b) {
    __half2 t = __floats2half2_rn(a, b);
    return *(uint32_t*)&t;
}
__device__ __forceinline__ uint32_t smem_u32(const void* p) {
    uint32_t a;
    asm("{ .reg .u64 t; cvta.to.shared.u64 t, %1; cvt.u32.u64 %0, t; }" : "=r"(a) : "l"(p));
    return a;
}
#define MMA16816BF(c, a0, a1, a2, a3, b0, b1)                                 \
    asm volatile("mma.sync.aligned.m16n8k16.row.col.f32.bf16.bf16.f32 "       \
                 "{%0,%1,%2,%3}, {%4,%5,%6,%7}, {%8,%9}, {%0,%1,%2,%3};"      \
                 : "+f"((c)[0]), "+f"((c)[1]), "+f"((c)[2]), "+f"((c)[3])     \
                 : "r"(a0), "r"(a1), "r"(a2), "r"(a3), "r"(b0), "r"(b1))
#define MMA16816F(c, a0, a1, a2, a3, b0, b1)                                  \
    asm volatile("mma.sync.aligned.m16n8k16.row.col.f32.f16.f16.f32 "         \
                 "{%0,%1,%2,%3}, {%4,%5,%6,%7}, {%8,%9}, {%0,%1,%2,%3};"      \
                 : "+f"((c)[0]), "+f"((c)[1]), "+f"((c)[2]), "+f"((c)[3])     \
                 : "r"(a0), "r"(a1), "r"(a2), "r"(a3), "r"(b0), "r"(b1))
#define LDSM4(r, addr)                                                        \
    asm volatile("ldmatrix.sync.aligned.m8n8.x4.shared.b16 {%0,%1,%2,%3}, [%4];" \
                 : "=r"((r)[0]), "=r"((r)[1]), "=r"((r)[2]), "=r"((r)[3])     \
                 : "r"(addr))

#define LSTRIDE 136
#define AH_OFF 0
#define AL_OFF 17408
#define WH_OFF 34816
#define WL_OFF 69632
#define SMEM_X1 104448
#define FA_OFF 0
#define FW_OFF 17408
#define SMEM_F16 52224

// ================= CSR build =================
__global__ void zero_k(int* deg, int* cur) {
    int i = blockIdx.x * 256 + threadIdx.x;
    if (i < NN) { deg[i] = 0; cur[i] = 0; }
}
__global__ void hist_k(const int* __restrict__ dst, int* __restrict__ deg) {
    int e = blockIdx.x * 256 + threadIdx.x;
    if (e < EE) atomicAdd(&deg[__ldg(&dst[e])], 1);
}
__global__ void scan_k(const int* __restrict__ deg, int* __restrict__ off) {
    __shared__ int bs[1024];
    const int t = threadIdx.x;
    const int CH = (NN + 1023) / 1024;           // 49
    int base0 = t * CH;
    int s = 0;
    for (int j = 0; j < CH; j++) {
        int idx = base0 + j;
        if (idx < NN) s += deg[idx];
    }
    bs[t] = s;
    __syncthreads();
    for (int o = 1; o < 1024; o <<= 1) {
        int tmp = (t >= o) ? bs[t - o] : 0;
        __syncthreads();
        bs[t] += tmp;
        __syncthreads();
    }
    int run = bs[t] - s;                         // exclusive base
    for (int j = 0; j < CH; j++) {
        int idx = base0 + j;
        if (idx < NN) { off[idx] = run; run += deg[idx]; }
    }
    if (t == 1023) off[NN] = bs[1023];
}
__global__ void fill_k(const int* __restrict__ src, const int* __restrict__ dst,
                       const int* __restrict__ h, const int* __restrict__ rel,
                       const float* __restrict__ norm,
                       const int* __restrict__ off, int* __restrict__ cur,
                       int* __restrict__ trow0, int* __restrict__ trow1,
                       float* __restrict__ enorm) {
    int e = blockIdx.x * 256 + threadIdx.x;
    if (e >= EE) return;
    int s = __ldg(&src[e]);
    int d = __ldg(&dst[e]);
    int rr = __ldg(&rel[e]);
    int pos = atomicAdd(&cur[d], 1);
    int idx = __ldg(&off[d]) + pos;
    trow0[idx] = rr * NN + __ldg(&h[s]);
    trow1[idx] = rr * NN + s;
    enorm[idx] = __ldg(&norm[e]);
}

// ================= prep =================
__global__ void prep_w1t(const float* __restrict__ bases1, const float* __restrict__ loop1,
                         __nv_bfloat16* __restrict__ whi, __nv_bfloat16* __restrict__ wlo,
                         __half* __restrict__ wf) {
    int i = blockIdx.x * 256 + threadIdx.x;
    if (i >= 5 * 16384) return;
    int s = i >> 14;
    int f = (i >> 7) & 127;
    int d = i & 127;
    float v = (s < 4) ? __ldg(&bases1[s * 16384 + d * 128 + f]) : __ldg(&loop1[d * 128 + f]);
    __nv_bfloat16 hi = __float2bfloat16(v);
    __nv_bfloat16 lo = __float2bfloat16(v - __bfloat162float(hi));
    whi[i] = hi;
    wlo[i] = lo;
    if (s < 4) wf[i] = __float2half(v);
}

__global__ void compose0_k(const float* __restrict__ b0, const float* __restrict__ wc,
                           __half* __restrict__ T0) {
    int i = blockIdx.x * 256 + threadIdx.x;
    if (i >= NN * 32) return;
    const float4* bp = (const float4*)b0;
    const long PS = (long)NN * 32;
    float4 v0 = __ldg(bp + i);
    float4 v1 = __ldg(bp + i + PS);
    float4 v2 = __ldg(bp + i + 2 * PS);
    float4 v3 = __ldg(bp + i + 3 * PS);
    uint2* tp = (uint2*)T0;
#pragma unroll
    for (int r = 0; r < RR; r++) {
        float c0 = __ldg(&wc[r * 4 + 0]), c1 = __ldg(&wc[r * 4 + 1]);
        float c2 = __ldg(&wc[r * 4 + 2]), c3 = __ldg(&wc[r * 4 + 3]);
        float mx = c0 * v0.x + c1 * v1.x + c2 * v2.x + c3 * v3.x;
        float my = c0 * v0.y + c1 * v1.y + c2 * v2.y + c3 * v3.y;
        float mz = c0 * v0.z + c1 * v1.z + c2 * v2.z + c3 * v3.z;
        float mw = c0 * v0.w + c1 * v1.w + c2 * v2.w + c3 * v3.w;
        uint2 u = { pack_f16(mx, my), pack_f16(mz, mw) };
        tp[(size_t)r * PS + i] = u;
    }
}

__global__ void compose1_k(const __half* __restrict__ Yh, const float* __restrict__ wc,
                           __half* __restrict__ T1) {
    int i = blockIdx.x * 256 + threadIdx.x;
    if (i >= NN * 32) return;
    const uint2* yp = (const uint2*)Yh;
    const long PS = (long)NN * 32;
    uint2 u0 = __ldg(yp + i);
    uint2 u1 = __ldg(yp + i + PS);
    uint2 u2 = __ldg(yp + i + 2 * PS);
    uint2 u3 = __ldg(yp + i + 3 * PS);
    float2 a0 = __half22float2(*(const __half2*)&u0.x), b0 = __half22float2(*(const __half2*)&u0.y);
    float2 a1 = __half22float2(*(const __half2*)&u1.x), b1 = __half22float2(*(const __half2*)&u1.y);
    float2 a2 = __half22float2(*(const __half2*)&u2.x), b2 = __half22float2(*(const __half2*)&u2.y);
    float2 a3 = __half22float2(*(const __half2*)&u3.x), b3 = __half22float2(*(const __half2*)&u3.y);
    uint2* tp = (uint2*)T1;
#pragma unroll
    for (int r = 0; r < RR; r++) {
        float c0 = __ldg(&wc[r * 4 + 0]), c1 = __ldg(&wc[r * 4 + 1]);
        float c2 = __ldg(&wc[r * 4 + 2]), c3 = __ldg(&wc[r * 4 + 3]);
        float mx = c0 * a0.x + c1 * a1.x + c2 * a2.x + c3 * a3.x;
        float my = c0 * a0.y + c1 * a1.y + c2 * a2.y + c3 * a3.y;
        float mz = c0 * b0.x + c1 * b1.x + c2 * b2.x + c3 * b3.x;
        float mw = c0 * b0.y + c1 * b1.y + c2 * b2.y + c3 * b3.y;
        uint2 u = { pack_f16(mx, my), pack_f16(mz, mw) };
        tp[(size_t)r * PS + i] = u;
    }
}

__global__ void compose2_k(const float* __restrict__ Z, const float* __restrict__ wc,
                           __half* __restrict__ T2) {
    int i = blockIdx.x * 256 + threadIdx.x;
    if (i >= NN * 4) return;
    const float4* zp = (const float4*)Z;
    const long PS = (long)NN * 4;
    float4 v0 = __ldg(zp + i);
    float4 v1 = __ldg(zp + i + PS);
    float4 v2 = __ldg(zp + i + 2 * PS);
    float4 v3 = __ldg(zp + i + 3 * PS);
    uint2* tp = (uint2*)T2;
#pragma unroll
    for (int r = 0; r < RR; r++) {
        float c0 = __ldg(&wc[r * 4 + 0]), c1 = __ldg(&wc[r * 4 + 1]);
        float c2 = __ldg(&wc[r * 4 + 2]), c3 = __ldg(&wc[r * 4 + 3]);
        float mx = c0 * v0.x + c1 * v1.x + c2 * v2.x + c3 * v3.x;
        float my = c0 * v0.y + c1 * v1.y + c2 * v2.y + c3 * v3.y;
        float mz = c0 * v0.z + c1 * v1.z + c2 * v2.z + c3 * v3.z;
        float mw = c0 * v0.w + c1 * v1.w + c2 * v2.w + c3 * v3.w;
        uint2 u = { pack_f16(mx, my), pack_f16(mz, mw) };
        tp[(size_t)r * PS + i] = u;
    }
}

// ---------------- layer 0 init ----------------
__global__ void init0_k(const int* __restrict__ h, const float* __restrict__ loop0,
                        const float* __restrict__ bias0, float* __restrict__ out) {
    int i = blockIdx.x * 256 + threadIdx.x;
    if (i >= NN * HH) return;
    int n = i >> 7;
    int f = i & 127;
    int id = __ldg(&h[n]);
    out[i] = __ldg(&loop0[(size_t)id * HH + f]) + __ldg(&bias0[f]);
}

// ================= aggregators (owner-computes; no atomics) =================
// H=128: one warp per dst node; 2-edge unrolled gather; single 512B RMW.
__global__ void __launch_bounds__(256) aggH_k(
    const int* __restrict__ off, const int* __restrict__ trow,
    const float* __restrict__ enorm, const __half* __restrict__ T,
    float* __restrict__ out) {
    int d = blockIdx.x * 8 + (threadIdx.x >> 5);
    if (d >= NN) return;
    int lane = threadIdx.x & 31;
    int beg = __ldg(&off[d]);
    int end = __ldg(&off[d + 1]);
    if (beg == end) return;
    const uint2* tp = (const uint2*)T;
    float4 acc = {0.f, 0.f, 0.f, 0.f};
    int i = beg;
    for (; i + 1 < end; i += 2) {
        int tr0 = __ldg(&trow[i]);
        int tr1 = __ldg(&trow[i + 1]);
        float n0 = __ldg(&enorm[i]);
        float n1 = __ldg(&enorm[i + 1]);
        uint2 u0 = __ldg(tp + (size_t)tr0 * 32 + lane);
        uint2 u1 = __ldg(tp + (size_t)tr1 * 32 + lane);
        float2 a0 = __half22float2(*(const __half2*)&u0.x), b0 = __half22float2(*(const __half2*)&u0.y);
        float2 a1 = __half22float2(*(const __half2*)&u1.x), b1 = __half22float2(*(const __half2*)&u1.y);
        acc.x += a0.x * n0 + a1.x * n1;
        acc.y += a0.y * n0 + a1.y * n1;
        acc.z += b0.x * n0 + b1.x * n1;
        acc.w += b0.y * n0 + b1.y * n1;
    }
    if (i < end) {
        int tr0 = __ldg(&trow[i]);
        float n0 = __ldg(&enorm[i]);
        uint2 u0 = __ldg(tp + (size_t)tr0 * 32 + lane);
        float2 a0 = __half22float2(*(const __half2*)&u0.x), b0 = __half22float2(*(const __half2*)&u0.y);
        acc.x += a0.x * n0; acc.y += a0.y * n0;
        acc.z += b0.x * n0; acc.w += b0.y * n0;
    }
    float4* op = (float4*)(out + (long)d * HH) + lane;
    float4 cur = *op;
    cur.x += acc.x; cur.y += acc.y; cur.z += acc.z; cur.w += acc.w;
    *op = cur;
}

// C=16: thread handles (dst, quarter); 4 threads per dst.
__global__ void __launch_bounds__(256) agg2_k(
    const int* __restrict__ off, const int* __restrict__ trow,
    const float* __restrict__ enorm, const __half* __restrict__ T2,
    float* __restrict__ out) {
    int tid = blockIdx.x * 256 + threadIdx.x;
    int d = tid >> 2;
    if (d >= NN) return;
    int q = tid & 3;
    int beg = __ldg(&off[d]);
    int end = __ldg(&off[d + 1]);
    if (beg == end) return;
    const uint2* tp = (const uint2*)T2;
    float4 acc = {0.f, 0.f, 0.f, 0.f};
    int i = beg;
    for (; i + 1 < end; i += 2) {
        int tr0 = __ldg(&trow[i]);
        int tr1 = __ldg(&trow[i + 1]);
        float n0 = __ldg(&enorm[i]);
        float n1 = __ldg(&enorm[i + 1]);
        uint2 u0 = __ldg(tp + (size_t)tr0 * 4 + q);
        uint2 u1 = __ldg(tp + (size_t)tr1 * 4 + q);
        float2 a0 = __half22float2(*(const __half2*)&u0.x), b0 = __half22float2(*(const __half2*)&u0.y);
        float2 a1 = __half22float2(*(const __half2*)&u1.x), b1 = __half22float2(*(const __half2*)&u1.y);
        acc.x += a0.x * n0 + a1.x * n1;
        acc.y += a0.y * n0 + a1.y * n1;
        acc.z += b0.x * n0 + b1.x * n1;
        acc.w += b0.y * n0 + b1.y * n1;
    }
    if (i < end) {
        int tr0 = __ldg(&trow[i]);
        float n0 = __ldg(&enorm[i]);
        uint2 u0 = __ldg(tp + (size_t)tr0 * 4 + q);
        float2 a0 = __half22float2(*(const __half2*)&u0.x), b0 = __half22float2(*(const __half2*)&u0.y);
        acc.x += a0.x * n0; acc.y += a0.y * n0;
        acc.z += b0.x * n0; acc.w += b0.y * n0;
    }
    float4* op = (float4*)(out + (long)d * CC) + q;
    float4 cur = *op;
    cur.x += acc.x; cur.y += acc.y; cur.z += acc.z; cur.w += acc.w;
    *op = cur;
}

// ---------------- fp16 HMMA: Y_b = relu(x0) @ B1_b ----------------
__global__ void __launch_bounds__(256, 3) mma_f16(
    const float* __restrict__ X, const __half* __restrict__ Wf,
    __half* __restrict__ Yh) {
    extern __shared__ char sm[];
    const int tid = threadIdx.x;
    const int w = tid >> 5;
    const int lane = tid & 31;
    const int slice = blockIdx.y;
    const int row0 = blockIdx.x * 64;
    {
        const uint2* g = (const uint2*)(Wf + slice * 16384);
#pragma unroll
        for (int i = 0; i < 16; i++) {
            int r = w * 16 + i;
            uint2 v = __ldg(g + r * 32 + lane);
            *(uint2*)(sm + FW_OFF + r * (LSTRIDE * 2) + lane * 8) = v;
        }
    }
    {
#pragma unroll
        for (int i = 0; i < 8; i++) {
            int r = w * 8 + i;
            int rg = row0 + r;
            float4 q = (rg < NN) ? __ldg((const float4*)X + (long)rg * 32 + lane)
                                 : make_float4(0.f, 0.f, 0.f, 0.f);
            uint2 u = { pack_f16(fmaxf(q.x, 0.f), fmaxf(q.y, 0.f)),
                        pack_f16(fmaxf(q.z, 0.f), fmaxf(q.w, 0.f)) };
            *(uint2*)(sm + FA_OFF + r * (LSTRIDE * 2) + lane * 8) = u;
        }
    }
    __syncthreads();

    const int wm = w & 1, wn = w >> 1;
    const int r0 = wm * 32, c0 = wn * 32;
    const uint32_t lrow = lane & 15;
    const uint32_t lkh = (lane >> 4) << 3;
    const uint32_t sA = smem_u32(sm + FA_OFF), sW = smem_u32(sm + FW_OFF);

    float acc[2][4][4];
#pragma unroll
    for (int mi = 0; mi < 2; mi++)
#pragma unroll
        for (int j = 0; j < 4; j++)
            acc[mi][j][0] = acc[mi][j][1] = acc[mi][j][2] = acc[mi][j][3] = 0.f;

#pragma unroll
    for (int ks = 0; ks < 8; ks++) {
        const uint32_t kb = ks * 16 + lkh;
        uint32_t A[2][4], B[2][4];
#pragma unroll
        for (int mi = 0; mi < 2; mi++)
            LDSM4(A[mi], sA + ((r0 + mi * 16 + lrow) * LSTRIDE + kb) * 2);
#pragma unroll
        for (int nj = 0; nj < 2; nj++)
            LDSM4(B[nj], sW + ((c0 + nj * 16 + lrow) * LSTRIDE + kb) * 2);
#pragma unroll
        for (int mi = 0; mi < 2; mi++)
#pragma unroll
            for (int nj = 0; nj < 2; nj++) {
                MMA16816F(acc[mi][nj * 2],     A[mi][0], A[mi][1], A[mi][2], A[mi][3], B[nj][0], B[nj][2]);
                MMA16816F(acc[mi][nj * 2 + 1], A[mi][0], A[mi][1], A[mi][2], A[mi][3], B[nj][1], B[nj][3]);
            }
    }

    __half* O = Yh + (size_t)slice * NN * HH;
    const int g = lane >> 2, tg = lane & 3;
#pragma unroll
    for (int mi = 0; mi < 2; mi++) {
        long ra = row0 + r0 + mi * 16 + g;
        long rb = ra + 8;
#pragma unroll
        for (int j = 0; j < 4; j++) {
            int col = c0 + j * 8 + tg * 2;
            if (ra < NN) *(uint32_t*)(O + ra * 128 + col) = pack_f16(acc[mi][j][0], acc[mi][j][1]);
            if (rb < NN) *(uint32_t*)(O + rb * 128 + col) = pack_f16(acc[mi][j][2], acc[mi][j][3]);
        }
    }
}

// ---------------- bf16 hi/lo HMMA: x1 = relu(x0) @ loop1 + bias1 ----------------
__global__ void __launch_bounds__(256, 2) mma_x1(
    const float* __restrict__ X,
    const __nv_bfloat16* __restrict__ Wth, const __nv_bfloat16* __restrict__ Wtl,
    float* __restrict__ x1, const float* __restrict__ bias1) {
    extern __shared__ char sm[];
    const int tid = threadIdx.x;
    const int w = tid >> 5;
    const int lane = tid & 31;
    const int row0 = blockIdx.x * 64;
    {
        const uint2* gh = (const uint2*)(Wth + 4 * 16384);
        const uint2* gl = (const uint2*)(Wtl + 4 * 16384);
#pragma unroll
        for (int i = 0; i < 16; i++) {
            int r = w * 16 + i;
            uint2 vh = __ldg(gh + r * 32 + lane);
            uint2 vl = __ldg(gl + r * 32 + lane);
            *(uint2*)(sm + WH_OFF + r * (LSTRIDE * 2) + lane * 8) = vh;
            *(uint2*)(sm + WL_OFF + r * (LSTRIDE * 2) + lane * 8) = vl;
        }
    }
    {
#pragma unroll
        for (int i = 0; i < 8; i++) {
            int r = w * 8 + i;
            int rg = row0 + r;
            float4 q = (rg < NN) ? __ldg((const float4*)X + (long)rg * 32 + lane)
                                 : make_float4(0.f, 0.f, 0.f, 0.f);
            q.x = fmaxf(q.x, 0.f); q.y = fmaxf(q.y, 0.f);
            q.z = fmaxf(q.z, 0.f); q.w = fmaxf(q.w, 0.f);
            float hx = __bfloat162float(__float2bfloat16(q.x));
            float hy = __bfloat162float(__float2bfloat16(q.y));
            float hz = __bfloat162float(__float2bfloat16(q.z));
            float hw = __bfloat162float(__float2bfloat16(q.w));
            uint2 uh = { pack_bf16(q.x, q.y), pack_bf16(q.z, q.w) };
            uint2 ul = { pack_bf16(q.x - hx, q.y - hy), pack_bf16(q.z - hz, q.w - hw) };
            *(uint2*)(sm + AH_OFF + r * (LSTRIDE * 2) + lane * 8) = uh;
            *(uint2*)(sm + AL_OFF + r * (LSTRIDE * 2) + lane * 8) = ul;
        }
    }
    __syncthreads();

    const int wm = w & 1, wn = w >> 1;
    const int r0 = wm * 32, c0 = wn * 32;
    const uint32_t lrow = lane & 15;
    const uint32_t lkh = (lane >> 4) << 3;
    const uint32_t sAH = smem_u32(sm + AH_OFF), sAL = smem_u32(sm + AL_OFF);
    const uint32_t sWH = smem_u32(sm + WH_OFF), sWL = smem_u32(sm + WL_OFF);

    float acc[2][4][4];
#pragma unroll
    for (int mi = 0; mi < 2; mi++)
#pragma unroll
        for (int j = 0; j < 4; j++)
            acc[mi][j][0] = acc[mi][j][1] = acc[mi][j][2] = acc[mi][j][3] = 0.f;

#pragma unroll
    for (int ks = 0; ks < 8; ks++) {
        const uint32_t kb = ks * 16 + lkh;
        uint32_t AH[2][4], AL[2][4], BH[2][4], BL[2][4];
#pragma unroll
        for (int mi = 0; mi < 2; mi++) {
            uint32_t off = ((r0 + mi * 16 + lrow) * LSTRIDE + kb) * 2;
            LDSM4(AH[mi], sAH + off);
            LDSM4(AL[mi], sAL + off);
        }
#pragma unroll
        for (int nj = 0; nj < 2; nj++) {
            uint32_t off = ((c0 + nj * 16 + lrow) * LSTRIDE + kb) * 2;
            LDSM4(BH[nj], sWH + off);
            LDSM4(BL[nj], sWL + off);
        }
#pragma unroll
        for (int mi = 0; mi < 2; mi++)
#pragma unroll
            for (int nj = 0; nj < 2; nj++) {
                float* cA = acc[mi][nj * 2];
                float* cB = acc[mi][nj * 2 + 1];
                MMA16816BF(cA, AH[mi][0], AH[mi][1], AH[mi][2], AH[mi][3], BH[nj][0], BH[nj][2]);
                MMA16816BF(cA, AH[mi][0], AH[mi][1], AH[mi][2], AH[mi][3], BL[nj][0], BL[nj][2]);
                MMA16816BF(cA, AL[mi][0], AL[mi][1], AL[mi][2], AL[mi][3], BH[nj][0], BH[nj][2]);
                MMA16816BF(cB, AH[mi][0], AH[mi][1], AH[mi][2], AH[mi][3], BH[nj][1], BH[nj][3]);
                MMA16816BF(cB, AH[mi][0], AH[mi][1], AH[mi][2], AH[mi][3], BL[nj][1], BL[nj][3]);
                MMA16816BF(cB, AL[mi][0], AL[mi][1], AL[mi][2], AL[mi][3], BH[nj][1], BH[nj][3]);
            }
    }

    const int g = lane >> 2, tg = lane & 3;
#pragma unroll
    for (int mi = 0; mi < 2; mi++) {
        long ra = row0 + r0 + mi * 16 + g;
        long rb = ra + 8;
#pragma unroll
        for (int j = 0; j < 4; j++) {
            int col = c0 + j * 8 + tg * 2;
            float b0 = __ldg(&bias1[col]), b1 = __ldg(&bias1[col + 1]);
            if (ra < NN) {
                float2 v = { acc[mi][j][0] + b0, acc[mi][j][1] + b1 };
                *(float2*)(x1 + ra * 128 + col) = v;
            }
            if (rb < NN) {
                float2 v = { acc[mi][j][2] + b0, acc[mi][j][3] + b1 };
                *(float2*)(x1 + rb * 128 + col) = v;
            }
        }
    }
}

// ---------------- layer 2 transform, F=16 ----------------
__global__ void __launch_bounds__(128) transform16(
    const float* __restrict__ X, const float* __restrict__ bases2,
    const float* __restrict__ loop2, const float* __restrict__ bias2,
    float* __restrict__ Z, float* __restrict__ out) {
    __shared__ float ws[128 * 16];
    __shared__ float xs[64][129];
    const int y = blockIdx.y;
    const float* W = (y < 4) ? (bases2 + y * 2048) : loop2;
    float* O = (y < 4) ? (Z + (long)y * NN * CC) : out;
    const int t = threadIdx.x;
    const int col = t & 15, rg = t >> 4;
    const int row0 = blockIdx.x * 64;
    for (int i = t; i < 128 * 16; i += 128) ws[i] = __ldg(&W[i]);
#pragma unroll 4
    for (int i = 0; i < 64; i++) {
        int rr = row0 + i;
        float v = (rr < NN) ? __ldg(&X[(long)rr * 128 + t]) : 0.f;
        xs[i][t] = fmaxf(v, 0.f);
    }
    __syncthreads();
    const float bv = (y == 4) ? __ldg(&bias2[col]) : 0.f;
    for (int p = 0; p < 8; p++) {
        int rl = p * 8 + rg;
        float a = 0.f;
#pragma unroll 16
        for (int d = 0; d < 128; d++) a = fmaf(xs[rl][d], ws[d * 16 + col], a);
        int rr = row0 + rl;
        if (rr < NN) O[(long)rr * 16 + col] = a + bv;
    }
}

// ---------------- launch ----------------
extern "C" void kernel_launch(void* const* d_in, const int* in_sizes, int n_in,
                              void* d_out, int out_size) {
    const int*   src    = (const int*)d_in[0];
    const int*   dst    = (const int*)d_in[1];
    const int*   h      = (const int*)d_in[2];
    const int*   rtab   = (const int*)d_in[3];
    const float* norm   = (const float*)d_in[4];
    const float* bases0 = (const float*)d_in[5];
    const float* wcomp0 = (const float*)d_in[6];
    const float* loop0  = (const float*)d_in[7];
    const float* bias0  = (const float*)d_in[8];
    const float* bases1 = (const float*)d_in[9];
    const float* wcomp1 = (const float*)d_in[10];
    const float* loop1  = (const float*)d_in[11];
    const float* bias1  = (const float*)d_in[12];
    const float* bases2 = (const float*)d_in[13];
    const float* wcomp2 = (const float*)d_in[14];
    const float* loop2  = (const float*)d_in[15];
    const float* bias2  = (const float*)d_in[16];
    float* out = (float*)d_out;

    float *p_x0, *p_x1, *p_z2;
    __half *p_t0, *p_t1, *p_t2, *p_y1h, *p_wf;
    __nv_bfloat16 *p_whi, *p_wlo;
    int *p_deg, *p_cur, *p_off, *p_tr0, *p_tr1;
    float *p_en;
    cudaGetSymbolAddress((void**)&p_x0, g_x0);
    cudaGetSymbolAddress((void**)&p_x1, g_x1);
    cudaGetSymbolAddress((void**)&p_t0, g_t0);
    cudaGetSymbolAddress((void**)&p_t1, g_t1);
    cudaGetSymbolAddress((void**)&p_t2, g_t2);
    cudaGetSymbolAddress((void**)&p_y1h, g_y1h);
    cudaGetSymbolAddress((void**)&p_z2, g_z2);
    cudaGetSymbolAddress((void**)&p_whi, g_w1thi);
    cudaGetSymbolAddress((void**)&p_wlo, g_w1tlo);
    cudaGetSymbolAddress((void**)&p_wf, g_w1tf);
    cudaGetSymbolAddress((void**)&p_deg, g_deg);
    cudaGetSymbolAddress((void**)&p_cur, g_cur);
    cudaGetSymbolAddress((void**)&p_off, g_off);
    cudaGetSymbolAddress((void**)&p_tr0, g_trow0);
    cudaGetSymbolAddress((void**)&p_tr1, g_trow1);
    cudaGetSymbolAddress((void**)&p_en, g_enorm);

    static int attr_done = 0;
    if (!attr_done) {
        cudaFuncSetAttribute(mma_x1, cudaFuncAttributeMaxDynamicSharedMemorySize, SMEM_X1);
        cudaFuncSetAttribute(mma_f16, cudaFuncAttributeMaxDynamicSharedMemorySize, SMEM_F16);
        attr_done = 1;
    }

    const int nh_blocks = (NN * HH + 255) / 256;
    const int e_blocks  = (EE + 255) / 256;
    const int row_t64   = (NN + 63) / 64;
    const int ncvt      = (NN * 32 + 255) / 256;
    const int agg_blocks = (NN + 7) / 8;

    // ---- CSR build (graph fixed per call) ----
    zero_k<<<(NN + 255) / 256, 256>>>(p_deg, p_cur);
    hist_k<<<e_blocks, 256>>>(dst, p_deg);
    scan_k<<<1, 1024>>>(p_deg, p_off);
    fill_k<<<e_blocks, 256>>>(src, dst, h, rtab, norm, p_off, p_cur, p_tr0, p_tr1, p_en);

    // ---- prep ----
    prep_w1t<<<(5 * 16384 + 255) / 256, 256>>>(bases1, loop1, p_whi, p_wlo, p_wf);
    compose0_k<<<ncvt, 256>>>(bases0, wcomp0, p_t0);

    // ---- layer 0 ----
    init0_k<<<nh_blocks, 256>>>(h, loop0, bias0, p_x0);
    aggH_k<<<agg_blocks, 256>>>(p_off, p_tr0, p_en, p_t0, p_x0);

    // ---- layer 1 ----
    mma_f16<<<dim3(row_t64, 4), 256, SMEM_F16>>>(p_x0, p_wf, p_y1h);
    mma_x1<<<row_t64, 256, SMEM_X1>>>(p_x0, p_whi, p_wlo, p_x1, bias1);
    compose1_k<<<ncvt, 256>>>(p_y1h, wcomp1, p_t1);
    aggH_k<<<agg_blocks, 256>>>(p_off, p_tr1, p_en, p_t1, p_x1);

    // ---- layer 2 ----
    transform16<<<dim3(row_t64, 5), 128>>>(p_x1, bases2, loop2, bias2, p_z2, out);
    compose2_k<<<(NN * 4 + 255) / 256, 256>>>(p_z2, wcomp2, p_t2);
    agg2_k<<<(NN * 4 + 255) / 256, 256>>>(p_off, p_tr1, p_en, p_t2, out);
}

// round 15
// speedup vs baseline: 1.2333x; 1.0257x over previous
#include <cuda_runtime.h>
#include <cuda_bf16.h>
#include <cuda_fp16.h>
#include <cstdint>

#define NN 50000
#define HH 128
#define CC 16
#define RR 8
#define BB 4
#define EE 800000

// ---------------- scratch (device globals; no allocations) ----------------
__device__ float g_x0[(size_t)NN * HH];
__device__ float g_x1[(size_t)NN * HH];
__device__ __half g_t0[(size_t)RR * NN * HH];        // composed layer0 tables (102.4 MB)
__device__ __half g_t1[(size_t)RR * NN * HH];        // composed layer1 tables (102.4 MB)
__device__ __half g_t2[(size_t)RR * NN * CC];        // composed layer2 tables (12.8 MB)
__device__ __half g_y1h[(size_t)4 * NN * HH];
__device__ float g_z2[(size_t)4 * NN * CC];
__device__ __nv_bfloat16 g_w1thi[5 * 128 * 128];
__device__ __nv_bfloat16 g_w1tlo[5 * 128 * 128];
__device__ __half g_w1tf[4 * 128 * 128];
// CSR (built once per call)
__device__ int g_deg[NN];
__device__ int g_cur[NN];
__device__ int g_off[NN + 1];
__device__ int g_trow0[EE];                          // r*NN + h[src]
__device__ int g_trow1[EE];                          // r*NN + src
__device__ float g_enorm[EE];

// ---------------- helpers ----------------
__device__ __forceinline__ uint32_t pack_bf16(float a, float b) {
    __nv_bfloat162 t = __floats2bfloat162_rn(a, b);
    return *(uint32_t*)&t;
}
__device__ __forceinline__ uint32_t pack_f16(float a, float b) {
    __half2 t = __floats2half2_rn(a, b);
    return *(uint32_t*)&t;
}
__device__ __forceinline__ uint32_t smem_u32(const void* p) {
    uint32_t a;
    asm("{ .reg .u64 t; cvta.to.shared.u64 t, %1; cvt.u32.u64 %0, t; }" : "=r"(a) : "l"(p));
    return a;
}
#define MMA16816BF(c, a0, a1, a2, a3, b0, b1)                                 \
    asm volatile("mma.sync.aligned.m16n8k16.row.col.f32.bf16.bf16.f32 "       \
                 "{%0,%1,%2,%3}, {%4,%5,%6,%7}, {%8,%9}, {%0,%1,%2,%3};"      \
                 : "+f"((c)[0]), "+f"((c)[1]), "+f"((c)[2]), "+f"((c)[3])     \
                 : "r"(a0), "r"(a1), "r"(a2), "r"(a3), "r"(b0), "r"(b1))
#define MMA16816F(c, a0, a1, a2, a3, b0, b1)                                  \
    asm volatile("mma.sync.aligned.m16n8k16.row.col.f32.f16.f16.f32 "         \
                 "{%0,%1,%2,%3}, {%4,%5,%6,%7}, {%8,%9}, {%0,%1,%2,%3};"      \
                 : "+f"((c)[0]), "+f"((c)[1]), "+f"((c)[2]), "+f"((c)[3])     \
                 : "r"(a0), "r"(a1), "r"(a2), "r"(a3), "r"(b0), "r"(b1))
#define LDSM4(r, addr)                                                        \
    asm volatile("ldmatrix.sync.aligned.m8n8.x4.shared.b16 {%0,%1,%2,%3}, [%4];" \
                 : "=r"((r)[0]), "=r"((r)[1]), "=r"((r)[2]), "=r"((r)[3])     \
                 : "r"(addr))

#define LSTRIDE 136
#define AH_OFF 0
#define AL_OFF 17408
#define WH_OFF 34816
#define WL_OFF 69632
#define SMEM_X1 104448
#define FA_OFF 0
#define FW_OFF 17408
#define SMEM_F16 52224

// ================= CSR build =================
__global__ void zero_k(int* deg, int* cur) {
    int i = blockIdx.x * 256 + threadIdx.x;
    if (i < NN) { deg[i] = 0; cur[i] = 0; }
}
__global__ void hist_k(const int* __restrict__ dst, int* __restrict__ deg) {
    int e = blockIdx.x * 256 + threadIdx.x;
    if (e < EE) atomicAdd(&deg[__ldg(&dst[e])], 1);
}
__global__ void scan_k(const int* __restrict__ deg, int* __restrict__ off) {
    __shared__ int bs[1024];
    const int t = threadIdx.x;
    const int CH = (NN + 1023) / 1024;
    int base0 = t * CH;
    int s = 0;
    for (int j = 0; j < CH; j++) {
        int idx = base0 + j;
        if (idx < NN) s += deg[idx];
    }
    bs[t] = s;
    __syncthreads();
    for (int o = 1; o < 1024; o <<= 1) {
        int tmp = (t >= o) ? bs[t - o] : 0;
        __syncthreads();
        bs[t] += tmp;
        __syncthreads();
    }
    int run = bs[t] - s;
    for (int j = 0; j < CH; j++) {
        int idx = base0 + j;
        if (idx < NN) { off[idx] = run; run += deg[idx]; }
    }
    if (t == 1023) off[NN] = bs[1023];
}
__global__ void fill_k(const int* __restrict__ src, const int* __restrict__ dst,
                       const int* __restrict__ h, const int* __restrict__ rel,
                       const float* __restrict__ norm,
                       const int* __restrict__ off, int* __restrict__ cur,
                       int* __restrict__ trow0, int* __restrict__ trow1,
                       float* __restrict__ enorm) {
    int e = blockIdx.x * 256 + threadIdx.x;
    if (e >= EE) return;
    int s = __ldg(&src[e]);
    int d = __ldg(&dst[e]);
    int rr = __ldg(&rel[e]);
    int pos = atomicAdd(&cur[d], 1);
    int idx = __ldg(&off[d]) + pos;
    trow0[idx] = rr * NN + __ldg(&h[s]);
    trow1[idx] = rr * NN + s;
    enorm[idx] = __ldg(&norm[e]);
}

// ================= prep =================
__global__ void prep_w1t(const float* __restrict__ bases1, const float* __restrict__ loop1,
                         __nv_bfloat16* __restrict__ whi, __nv_bfloat16* __restrict__ wlo,
                         __half* __restrict__ wf) {
    int i = blockIdx.x * 256 + threadIdx.x;
    if (i >= 5 * 16384) return;
    int s = i >> 14;
    int f = (i >> 7) & 127;
    int d = i & 127;
    float v = (s < 4) ? __ldg(&bases1[s * 16384 + d * 128 + f]) : __ldg(&loop1[d * 128 + f]);
    __nv_bfloat16 hi = __float2bfloat16(v);
    __nv_bfloat16 lo = __float2bfloat16(v - __bfloat162float(hi));
    whi[i] = hi;
    wlo[i] = lo;
    if (s < 4) wf[i] = __float2half(v);
}

__global__ void compose0_k(const float* __restrict__ b0, const float* __restrict__ wc,
                           __half* __restrict__ T0) {
    int i = blockIdx.x * 256 + threadIdx.x;
    if (i >= NN * 32) return;
    const float4* bp = (const float4*)b0;
    const long PS = (long)NN * 32;
    float4 v0 = __ldg(bp + i);
    float4 v1 = __ldg(bp + i + PS);
    float4 v2 = __ldg(bp + i + 2 * PS);
    float4 v3 = __ldg(bp + i + 3 * PS);
    uint2* tp = (uint2*)T0;
#pragma unroll
    for (int r = 0; r < RR; r++) {
        float c0 = __ldg(&wc[r * 4 + 0]), c1 = __ldg(&wc[r * 4 + 1]);
        float c2 = __ldg(&wc[r * 4 + 2]), c3 = __ldg(&wc[r * 4 + 3]);
        float mx = c0 * v0.x + c1 * v1.x + c2 * v2.x + c3 * v3.x;
        float my = c0 * v0.y + c1 * v1.y + c2 * v2.y + c3 * v3.y;
        float mz = c0 * v0.z + c1 * v1.z + c2 * v2.z + c3 * v3.z;
        float mw = c0 * v0.w + c1 * v1.w + c2 * v2.w + c3 * v3.w;
        uint2 u = { pack_f16(mx, my), pack_f16(mz, mw) };
        tp[(size_t)r * PS + i] = u;
    }
}

__global__ void compose1_k(const __half* __restrict__ Yh, const float* __restrict__ wc,
                           __half* __restrict__ T1) {
    int i = blockIdx.x * 256 + threadIdx.x;
    if (i >= NN * 32) return;
    const uint2* yp = (const uint2*)Yh;
    const long PS = (long)NN * 32;
    uint2 u0 = __ldg(yp + i);
    uint2 u1 = __ldg(yp + i + PS);
    uint2 u2 = __ldg(yp + i + 2 * PS);
    uint2 u3 = __ldg(yp + i + 3 * PS);
    float2 a0 = __half22float2(*(const __half2*)&u0.x), b0 = __half22float2(*(const __half2*)&u0.y);
    float2 a1 = __half22float2(*(const __half2*)&u1.x), b1 = __half22float2(*(const __half2*)&u1.y);
    float2 a2 = __half22float2(*(const __half2*)&u2.x), b2 = __half22float2(*(const __half2*)&u2.y);
    float2 a3 = __half22float2(*(const __half2*)&u3.x), b3 = __half22float2(*(const __half2*)&u3.y);
    uint2* tp = (uint2*)T1;
#pragma unroll
    for (int r = 0; r < RR; r++) {
        float c0 = __ldg(&wc[r * 4 + 0]), c1 = __ldg(&wc[r * 4 + 1]);
        float c2 = __ldg(&wc[r * 4 + 2]), c3 = __ldg(&wc[r * 4 + 3]);
        float mx = c0 * a0.x + c1 * a1.x + c2 * a2.x + c3 * a3.x;
        float my = c0 * a0.y + c1 * a1.y + c2 * a2.y + c3 * a3.y;
        float mz = c0 * b0.x + c1 * b1.x + c2 * b2.x + c3 * b3.x;
        float mw = c0 * b0.y + c1 * b1.y + c2 * b2.y + c3 * b3.y;
        uint2 u = { pack_f16(mx, my), pack_f16(mz, mw) };
        tp[(size_t)r * PS + i] = u;
    }
}

__global__ void compose2_k(const float* __restrict__ Z, const float* __restrict__ wc,
                           __half* __restrict__ T2) {
    int i = blockIdx.x * 256 + threadIdx.x;
    if (i >= NN * 4) return;
    const float4* zp = (const float4*)Z;
    const long PS = (long)NN * 4;
    float4 v0 = __ldg(zp + i);
    float4 v1 = __ldg(zp + i + PS);
    float4 v2 = __ldg(zp + i + 2 * PS);
    float4 v3 = __ldg(zp + i + 3 * PS);
    uint2* tp = (uint2*)T2;
#pragma unroll
    for (int r = 0; r < RR; r++) {
        float c0 = __ldg(&wc[r * 4 + 0]), c1 = __ldg(&wc[r * 4 + 1]);
        float c2 = __ldg(&wc[r * 4 + 2]), c3 = __ldg(&wc[r * 4 + 3]);
        float mx = c0 * v0.x + c1 * v1.x + c2 * v2.x + c3 * v3.x;
        float my = c0 * v0.y + c1 * v1.y + c2 * v2.y + c3 * v3.y;
        float mz = c0 * v0.z + c1 * v1.z + c2 * v2.z + c3 * v3.z;
        float mw = c0 * v0.w + c1 * v1.w + c2 * v2.w + c3 * v3.w;
        uint2 u = { pack_f16(mx, my), pack_f16(mz, mw) };
        tp[(size_t)r * PS + i] = u;
    }
}

// ---------------- layer 0 init ----------------
__global__ void init0_k(const int* __restrict__ h, const float* __restrict__ loop0,
                        const float* __restrict__ bias0, float* __restrict__ out) {
    int i = blockIdx.x * 256 + threadIdx.x;
    if (i >= NN * HH) return;
    int n = i >> 7;
    int f = i & 127;
    int id = __ldg(&h[n]);
    out[i] = __ldg(&loop0[(size_t)id * HH + f]) + __ldg(&bias0[f]);
}

// ================= aggregators (owner-computes; no atomics) =================
__global__ void __launch_bounds__(256) aggH_k(
    const int* __restrict__ off, const int* __restrict__ trow,
    const float* __restrict__ enorm, const __half* __restrict__ T,
    float* __restrict__ out) {
    int d = blockIdx.x * 8 + (threadIdx.x >> 5);
    if (d >= NN) return;
    int lane = threadIdx.x & 31;
    int beg = __ldg(&off[d]);
    int end = __ldg(&off[d + 1]);
    if (beg == end) return;
    const uint2* tp = (const uint2*)T;
    float4 acc = {0.f, 0.f, 0.f, 0.f};
    int i = beg;
    for (; i + 1 < end; i += 2) {
        int tr0 = __ldg(&trow[i]);
        int tr1 = __ldg(&trow[i + 1]);
        float n0 = __ldg(&enorm[i]);
        float n1 = __ldg(&enorm[i + 1]);
        uint2 u0 = __ldg(tp + (size_t)tr0 * 32 + lane);
        uint2 u1 = __ldg(tp + (size_t)tr1 * 32 + lane);
        float2 a0 = __half22float2(*(const __half2*)&u0.x), b0 = __half22float2(*(const __half2*)&u0.y);
        float2 a1 = __half22float2(*(const __half2*)&u1.x), b1 = __half22float2(*(const __half2*)&u1.y);
        acc.x += a0.x * n0 + a1.x * n1;
        acc.y += a0.y * n0 + a1.y * n1;
        acc.z += b0.x * n0 + b1.x * n1;
        acc.w += b0.y * n0 + b1.y * n1;
    }
    if (i < end) {
        int tr0 = __ldg(&trow[i]);
        float n0 = __ldg(&enorm[i]);
        uint2 u0 = __ldg(tp + (size_t)tr0 * 32 + lane);
        float2 a0 = __half22float2(*(const __half2*)&u0.x), b0 = __half22float2(*(const __half2*)&u0.y);
        acc.x += a0.x * n0; acc.y += a0.y * n0;
        acc.z += b0.x * n0; acc.w += b0.y * n0;
    }
    float4* op = (float4*)(out + (long)d * HH) + lane;
    float4 cur = *op;
    cur.x += acc.x; cur.y += acc.y; cur.z += acc.z; cur.w += acc.w;
    *op = cur;
}

__global__ void __launch_bounds__(256) agg2_k(
    const int* __restrict__ off, const int* __restrict__ trow,
    const float* __restrict__ enorm, const __half* __restrict__ T2,
    float* __restrict__ out) {
    int tid = blockIdx.x * 256 + threadIdx.x;
    int d = tid >> 2;
    if (d >= NN) return;
    int q = tid & 3;
    int beg = __ldg(&off[d]);
    int end = __ldg(&off[d + 1]);
    if (beg == end) return;
    const uint2* tp = (const uint2*)T2;
    float4 acc = {0.f, 0.f, 0.f, 0.f};
    int i = beg;
    for (; i + 1 < end; i += 2) {
        int tr0 = __ldg(&trow[i]);
        int tr1 = __ldg(&trow[i + 1]);
        float n0 = __ldg(&enorm[i]);
        float n1 = __ldg(&enorm[i + 1]);
        uint2 u0 = __ldg(tp + (size_t)tr0 * 4 + q);
        uint2 u1 = __ldg(tp + (size_t)tr1 * 4 + q);
        float2 a0 = __half22float2(*(const __half2*)&u0.x), b0 = __half22float2(*(const __half2*)&u0.y);
        float2 a1 = __half22float2(*(const __half2*)&u1.x), b1 = __half22float2(*(const __half2*)&u1.y);
        acc.x += a0.x * n0 + a1.x * n1;
        acc.y += a0.y * n0 + a1.y * n1;
        acc.z += b0.x * n0 + b1.x * n1;
        acc.w += b0.y * n0 + b1.y * n1;
    }
    if (i < end) {
        int tr0 = __ldg(&trow[i]);
        float n0 = __ldg(&enorm[i]);
        uint2 u0 = __ldg(tp + (size_t)tr0 * 4 + q);
        float2 a0 = __half22float2(*(const __half2*)&u0.x), b0 = __half22float2(*(const __half2*)&u0.y);
        acc.x += a0.x * n0; acc.y += a0.y * n0;
        acc.z += b0.x * n0; acc.w += b0.y * n0;
    }
    float4* op = (float4*)(out + (long)d * CC) + q;
    float4 cur = *op;
    cur.x += acc.x; cur.y += acc.y; cur.z += acc.z; cur.w += acc.w;
    *op = cur;
}

// ---------------- fp16 HMMA: Y_b = relu(x0) @ B1_b ----------------
__global__ void __launch_bounds__(256, 3) mma_f16(
    const float* __restrict__ X, const __half* __restrict__ Wf,
    __half* __restrict__ Yh) {
    extern __shared__ char sm[];
    const int tid = threadIdx.x;
    const int w = tid >> 5;
    const int lane = tid & 31;
    const int slice = blockIdx.y;
    const int row0 = blockIdx.x * 64;
    {
        const uint2* g = (const uint2*)(Wf + slice * 16384);
#pragma unroll
        for (int i = 0; i < 16; i++) {
            int r = w * 16 + i;
            uint2 v = __ldg(g + r * 32 + lane);
            *(uint2*)(sm + FW_OFF + r * (LSTRIDE * 2) + lane * 8) = v;
        }
    }
    {
#pragma unroll
        for (int i = 0; i < 8; i++) {
            int r = w * 8 + i;
            int rg = row0 + r;
            float4 q = (rg < NN) ? __ldg((const float4*)X + (long)rg * 32 + lane)
                                 : make_float4(0.f, 0.f, 0.f, 0.f);
            uint2 u = { pack_f16(fmaxf(q.x, 0.f), fmaxf(q.y, 0.f)),
                        pack_f16(fmaxf(q.z, 0.f), fmaxf(q.w, 0.f)) };
            *(uint2*)(sm + FA_OFF + r * (LSTRIDE * 2) + lane * 8) = u;
        }
    }
    __syncthreads();

    const int wm = w & 1, wn = w >> 1;
    const int r0 = wm * 32, c0 = wn * 32;
    const uint32_t lrow = lane & 15;
    const uint32_t lkh = (lane >> 4) << 3;
    const uint32_t sA = smem_u32(sm + FA_OFF), sW = smem_u32(sm + FW_OFF);

    float acc[2][4][4];
#pragma unroll
    for (int mi = 0; mi < 2; mi++)
#pragma unroll
        for (int j = 0; j < 4; j++)
            acc[mi][j][0] = acc[mi][j][1] = acc[mi][j][2] = acc[mi][j][3] = 0.f;

#pragma unroll
    for (int ks = 0; ks < 8; ks++) {
        const uint32_t kb = ks * 16 + lkh;
        uint32_t A[2][4], B[2][4];
#pragma unroll
        for (int mi = 0; mi < 2; mi++)
            LDSM4(A[mi], sA + ((r0 + mi * 16 + lrow) * LSTRIDE + kb) * 2);
#pragma unroll
        for (int nj = 0; nj < 2; nj++)
            LDSM4(B[nj], sW + ((c0 + nj * 16 + lrow) * LSTRIDE + kb) * 2);
#pragma unroll
        for (int mi = 0; mi < 2; mi++)
#pragma unroll
            for (int nj = 0; nj < 2; nj++) {
                MMA16816F(acc[mi][nj * 2],     A[mi][0], A[mi][1], A[mi][2], A[mi][3], B[nj][0], B[nj][2]);
                MMA16816F(acc[mi][nj * 2 + 1], A[mi][0], A[mi][1], A[mi][2], A[mi][3], B[nj][1], B[nj][3]);
            }
    }

    __half* O = Yh + (size_t)slice * NN * HH;
    const int g = lane >> 2, tg = lane & 3;
#pragma unroll
    for (int mi = 0; mi < 2; mi++) {
        long ra = row0 + r0 + mi * 16 + g;
        long rb = ra + 8;
#pragma unroll
        for (int j = 0; j < 4; j++) {
            int col = c0 + j * 8 + tg * 2;
            if (ra < NN) *(uint32_t*)(O + ra * 128 + col) = pack_f16(acc[mi][j][0], acc[mi][j][1]);
            if (rb < NN) *(uint32_t*)(O + rb * 128 + col) = pack_f16(acc[mi][j][2], acc[mi][j][3]);
        }
    }
}

// ---------------- bf16 hi/lo HMMA: x1 = relu(x0) @ loop1 + bias1 ----------------
__global__ void __launch_bounds__(256, 2) mma_x1(
    const float* __restrict__ X,
    const __nv_bfloat16* __restrict__ Wth, const __nv_bfloat16* __restrict__ Wtl,
    float* __restrict__ x1, const float* __restrict__ bias1) {
    extern __shared__ char sm[];
    const int tid = threadIdx.x;
    const int w = tid >> 5;
    const int lane = tid & 31;
    const int row0 = blockIdx.x * 64;
    {
        const uint2* gh = (const uint2*)(Wth + 4 * 16384);
        const uint2* gl = (const uint2*)(Wtl + 4 * 16384);
#pragma unroll
        for (int i = 0; i < 16; i++) {
            int r = w * 16 + i;
            uint2 vh = __ldg(gh + r * 32 + lane);
            uint2 vl = __ldg(gl + r * 32 + lane);
            *(uint2*)(sm + WH_OFF + r * (LSTRIDE * 2) + lane * 8) = vh;
            *(uint2*)(sm + WL_OFF + r * (LSTRIDE * 2) + lane * 8) = vl;
        }
    }
    {
#pragma unroll
        for (int i = 0; i < 8; i++) {
            int r = w * 8 + i;
            int rg = row0 + r;
            float4 q = (rg < NN) ? __ldg((const float4*)X + (long)rg * 32 + lane)
                                 : make_float4(0.f, 0.f, 0.f, 0.f);
            q.x = fmaxf(q.x, 0.f); q.y = fmaxf(q.y, 0.f);
            q.z = fmaxf(q.z, 0.f); q.w = fmaxf(q.w, 0.f);
            float hx = __bfloat162float(__float2bfloat16(q.x));
            float hy = __bfloat162float(__float2bfloat16(q.y));
            float hz = __bfloat162float(__float2bfloat16(q.z));
            float hw = __bfloat162float(__float2bfloat16(q.w));
            uint2 uh = { pack_bf16(q.x, q.y), pack_bf16(q.z, q.w) };
            uint2 ul = { pack_bf16(q.x - hx, q.y - hy), pack_bf16(q.z - hz, q.w - hw) };
            *(uint2*)(sm + AH_OFF + r * (LSTRIDE * 2) + lane * 8) = uh;
            *(uint2*)(sm + AL_OFF + r * (LSTRIDE * 2) + lane * 8) = ul;
        }
    }
    __syncthreads();

    const int wm = w & 1, wn = w >> 1;
    const int r0 = wm * 32, c0 = wn * 32;
    const uint32_t lrow = lane & 15;
    const uint32_t lkh = (lane >> 4) << 3;
    const uint32_t sAH = smem_u32(sm + AH_OFF), sAL = smem_u32(sm + AL_OFF);
    const uint32_t sWH = smem_u32(sm + WH_OFF), sWL = smem_u32(sm + WL_OFF);

    float acc[2][4][4];
#pragma unroll
    for (int mi = 0; mi < 2; mi++)
#pragma unroll
        for (int j = 0; j < 4; j++)
            acc[mi][j][0] = acc[mi][j][1] = acc[mi][j][2] = acc[mi][j][3] = 0.f;

#pragma unroll
    for (int ks = 0; ks < 8; ks++) {
        const uint32_t kb = ks * 16 + lkh;
        uint32_t AH[2][4], AL[2][4], BH[2][4], BL[2][4];
#pragma unroll
        for (int mi = 0; mi < 2; mi++) {
            uint32_t off = ((r0 + mi * 16 + lrow) * LSTRIDE + kb) * 2;
            LDSM4(AH[mi], sAH + off);
            LDSM4(AL[mi], sAL + off);
        }
#pragma unroll
        for (int nj = 0; nj < 2; nj++) {
            uint32_t off = ((c0 + nj * 16 + lrow) * LSTRIDE + kb) * 2;
            LDSM4(BH[nj], sWH + off);
            LDSM4(BL[nj], sWL + off);
        }
#pragma unroll
        for (int mi = 0; mi < 2; mi++)
#pragma unroll
            for (int nj = 0; nj < 2; nj++) {
                float* cA = acc[mi][nj * 2];
                float* cB = acc[mi][nj * 2 + 1];
                MMA16816BF(cA, AH[mi][0], AH[mi][1], AH[mi][2], AH[mi][3], BH[nj][0], BH[nj][2]);
                MMA16816BF(cA, AH[mi][0], AH[mi][1], AH[mi][2], AH[mi][3], BL[nj][0], BL[nj][2]);
                MMA16816BF(cA, AL[mi][0], AL[mi][1], AL[mi][2], AL[mi][3], BH[nj][0], BH[nj][2]);
                MMA16816BF(cB, AH[mi][0], AH[mi][1], AH[mi][2], AH[mi][3], BH[nj][1], BH[nj][3]);
                MMA16816BF(cB, AH[mi][0], AH[mi][1], AH[mi][2], AH[mi][3], BL[nj][1], BL[nj][3]);
                MMA16816BF(cB, AL[mi][0], AL[mi][1], AL[mi][2], AL[mi][3], BH[nj][1], BH[nj][3]);
            }
    }

    const int g = lane >> 2, tg = lane & 3;
#pragma unroll
    for (int mi = 0; mi < 2; mi++) {
        long ra = row0 + r0 + mi * 16 + g;
        long rb = ra + 8;
#pragma unroll
        for (int j = 0; j < 4; j++) {
            int col = c0 + j * 8 + tg * 2;
            float b0 = __ldg(&bias1[col]), b1 = __ldg(&bias1[col + 1]);
            if (ra < NN) {
                float2 v = { acc[mi][j][0] + b0, acc[mi][j][1] + b1 };
                *(float2*)(x1 + ra * 128 + col) = v;
            }
            if (rb < NN) {
                float2 v = { acc[mi][j][2] + b0, acc[mi][j][3] + b1 };
                *(float2*)(x1 + rb * 128 + col) = v;
            }
        }
    }
}

// ---------------- layer 2 transform, F=16; mode 0: bases->Z (grid.y=4), mode 1: loop->out+bias ----------------
__global__ void __launch_bounds__(128) transform16(
    const float* __restrict__ X, const float* __restrict__ bases2,
    const float* __restrict__ loop2, const float* __restrict__ bias2,
    float* __restrict__ Z, float* __restrict__ out, int mode) {
    __shared__ float ws[128 * 16];
    __shared__ float xs[64][129];
    const int y = blockIdx.y;
    const float* W = (mode == 0) ? (bases2 + y * 2048) : loop2;
    float* O = (mode == 0) ? (Z + (long)y * NN * CC) : out;
    const int t = threadIdx.x;
    const int col = t & 15, rg = t >> 4;
    const int row0 = blockIdx.x * 64;
    for (int i = t; i < 128 * 16; i += 128) ws[i] = __ldg(&W[i]);
#pragma unroll 4
    for (int i = 0; i < 64; i++) {
        int rr = row0 + i;
        float v = (rr < NN) ? __ldg(&X[(long)rr * 128 + t]) : 0.f;
        xs[i][t] = fmaxf(v, 0.f);
    }
    __syncthreads();
    const float bv = (mode == 1) ? __ldg(&bias2[col]) : 0.f;
    for (int p = 0; p < 8; p++) {
        int rl = p * 8 + rg;
        float a = 0.f;
#pragma unroll 16
        for (int d = 0; d < 128; d++) a = fmaf(xs[rl][d], ws[d * 16 + col], a);
        int rr = row0 + rl;
        if (rr < NN) O[(long)rr * 16 + col] = a + bv;
    }
}

// ---------------- launch ----------------
extern "C" void kernel_launch(void* const* d_in, const int* in_sizes, int n_in,
                              void* d_out, int out_size) {
    const int*   src    = (const int*)d_in[0];
    const int*   dst    = (const int*)d_in[1];
    const int*   h      = (const int*)d_in[2];
    const int*   rtab   = (const int*)d_in[3];
    const float* norm   = (const float*)d_in[4];
    const float* bases0 = (const float*)d_in[5];
    const float* wcomp0 = (const float*)d_in[6];
    const float* loop0  = (const float*)d_in[7];
    const float* bias0  = (const float*)d_in[8];
    const float* bases1 = (const float*)d_in[9];
    const float* wcomp1 = (const float*)d_in[10];
    const float* loop1  = (const float*)d_in[11];
    const float* bias1  = (const float*)d_in[12];
    const float* bases2 = (const float*)d_in[13];
    const float* wcomp2 = (const float*)d_in[14];
    const float* loop2  = (const float*)d_in[15];
    const float* bias2  = (const float*)d_in[16];
    float* out = (float*)d_out;

    float *p_x0, *p_x1, *p_z2;
    __half *p_t0, *p_t1, *p_t2, *p_y1h, *p_wf;
    __nv_bfloat16 *p_whi, *p_wlo;
    int *p_deg, *p_cur, *p_off, *p_tr0, *p_tr1;
    float *p_en;
    cudaGetSymbolAddress((void**)&p_x0, g_x0);
    cudaGetSymbolAddress((void**)&p_x1, g_x1);
    cudaGetSymbolAddress((void**)&p_t0, g_t0);
    cudaGetSymbolAddress((void**)&p_t1, g_t1);
    cudaGetSymbolAddress((void**)&p_t2, g_t2);
    cudaGetSymbolAddress((void**)&p_y1h, g_y1h);
    cudaGetSymbolAddress((void**)&p_z2, g_z2);
    cudaGetSymbolAddress((void**)&p_whi, g_w1thi);
    cudaGetSymbolAddress((void**)&p_wlo, g_w1tlo);
    cudaGetSymbolAddress((void**)&p_wf, g_w1tf);
    cudaGetSymbolAddress((void**)&p_deg, g_deg);
    cudaGetSymbolAddress((void**)&p_cur, g_cur);
    cudaGetSymbolAddress((void**)&p_off, g_off);
    cudaGetSymbolAddress((void**)&p_tr0, g_trow0);
    cudaGetSymbolAddress((void**)&p_tr1, g_trow1);
    cudaGetSymbolAddress((void**)&p_en, g_enorm);

    // one-time: func attrs + streams/events (created on correctness call, reused in capture)
    static int init_done = 0;
    static cudaStream_t s1, s2, s3;
    static cudaEvent_t evRoot, evCmp0, evPrep, evInit, evAgg0, evX1, evAgg1, evT16b, evEnd;
    if (!init_done) {
        cudaFuncSetAttribute(mma_x1, cudaFuncAttributeMaxDynamicSharedMemorySize, SMEM_X1);
        cudaFuncSetAttribute(mma_f16, cudaFuncAttributeMaxDynamicSharedMemorySize, SMEM_F16);
        cudaStreamCreateWithFlags(&s1, cudaStreamNonBlocking);
        cudaStreamCreateWithFlags(&s2, cudaStreamNonBlocking);
        cudaStreamCreateWithFlags(&s3, cudaStreamNonBlocking);
        cudaEventCreateWithFlags(&evRoot, cudaEventDisableTiming);
        cudaEventCreateWithFlags(&evCmp0, cudaEventDisableTiming);
        cudaEventCreateWithFlags(&evPrep, cudaEventDisableTiming);
        cudaEventCreateWithFlags(&evInit, cudaEventDisableTiming);
        cudaEventCreateWithFlags(&evAgg0, cudaEventDisableTiming);
        cudaEventCreateWithFlags(&evX1, cudaEventDisableTiming);
        cudaEventCreateWithFlags(&evAgg1, cudaEventDisableTiming);
        cudaEventCreateWithFlags(&evT16b, cudaEventDisableTiming);
        cudaEventCreateWithFlags(&evEnd, cudaEventDisableTiming);
        init_done = 1;
    }

    const int nh_blocks = (NN * HH + 255) / 256;
    const int e_blocks  = (EE + 255) / 256;
    const int row_t64   = (NN + 63) / 64;
    const int ncvt      = (NN * 32 + 255) / 256;
    const int agg_blocks = (NN + 7) / 8;

    // fork from the capture (legacy) stream
    cudaEventRecord(evRoot, 0);
    cudaStreamWaitEvent(s1, evRoot, 0);
    cudaStreamWaitEvent(s2, evRoot, 0);
    cudaStreamWaitEvent(s3, evRoot, 0);

    // s3: x0 base
    init0_k<<<nh_blocks, 256, 0, s3>>>(h, loop0, bias0, p_x0);
    cudaEventRecord(evInit, s3);

    // s2: compose0, then weight images
    compose0_k<<<ncvt, 256, 0, s2>>>(bases0, wcomp0, p_t0);
    cudaEventRecord(evCmp0, s2);
    prep_w1t<<<(5 * 16384 + 255) / 256, 256, 0, s2>>>(bases1, loop1, p_whi, p_wlo, p_wf);
    cudaEventRecord(evPrep, s2);

    // s1: CSR chain
    zero_k<<<(NN + 255) / 256, 256, 0, s1>>>(p_deg, p_cur);
    hist_k<<<e_blocks, 256, 0, s1>>>(dst, p_deg);
    scan_k<<<1, 1024, 0, s1>>>(p_deg, p_off);
    fill_k<<<e_blocks, 256, 0, s1>>>(src, dst, h, rtab, norm, p_off, p_cur, p_tr0, p_tr1, p_en);

    // s1: layer-0 aggregate (needs CSR + T0 + x0 base)
    cudaStreamWaitEvent(s1, evCmp0, 0);
    cudaStreamWaitEvent(s1, evInit, 0);
    aggH_k<<<agg_blocks, 256, 0, s1>>>(p_off, p_tr0, p_en, p_t0, p_x0);
    cudaEventRecord(evAgg0, s1);

    // s2: self-loop GEMM (needs x0 + W images; W images are s2-ordered)
    cudaStreamWaitEvent(s2, evAgg0, 0);
    mma_x1<<<row_t64, 256, SMEM_X1, s2>>>(p_x0, p_whi, p_wlo, p_x1, bias1);
    cudaEventRecord(evX1, s2);

    // s1: basis GEMMs + compose (needs prep)
    cudaStreamWaitEvent(s1, evPrep, 0);
    mma_f16<<<dim3(row_t64, 4), 256, SMEM_F16, s1>>>(p_x0, p_wf, p_y1h);
    compose1_k<<<ncvt, 256, 0, s1>>>(p_y1h, wcomp1, p_t1);
    cudaStreamWaitEvent(s1, evX1, 0);
    aggH_k<<<agg_blocks, 256, 0, s1>>>(p_off, p_tr1, p_en, p_t1, p_x1);
    cudaEventRecord(evAgg1, s1);

    // s2: layer-2 self-loop -> out (needs x1)
    cudaStreamWaitEvent(s2, evAgg1, 0);
    transform16<<<dim3(row_t64, 1), 128, 0, s2>>>(p_x1, bases2, loop2, bias2, p_z2, out, 1);
    cudaEventRecord(evT16b, s2);

    // s1: layer-2 basis path
    transform16<<<dim3(row_t64, 4), 128, 0, s1>>>(p_x1, bases2, loop2, bias2, p_z2, out, 0);
    compose2_k<<<(NN * 4 + 255) / 256, 256, 0, s1>>>(p_z2, wcomp2, p_t2);
    cudaStreamWaitEvent(s1, evT16b, 0);
    agg2_k<<<(NN * 4 + 255) / 256, 256, 0, s1>>>(p_off, p_tr1, p_en, p_t2, out);
    cudaEventRecord(evEnd, s1);

    // join back to the capture stream
    cudaStreamWaitEvent(0, evEnd, 0);
}

// round 16
// speedup vs baseline: 1.2356x; 1.0019x over previous
#include <cuda_runtime.h>
#include <cuda_bf16.h>
#include <cuda_fp16.h>
#include <cstdint>

#define NN 50000
#define HH 128
#define CC 16
#define RR 8
#define BB 4
#define EE 800000

// ---------------- scratch (device globals; no allocations) ----------------
__device__ float g_x0[(size_t)NN * HH];
__device__ float g_x1[(size_t)NN * HH];
__device__ __half g_t0[(size_t)RR * NN * HH];        // composed layer0 tables (102.4 MB)
__device__ __half g_t2[(size_t)RR * NN * CC];        // composed layer2 tables (12.8 MB)
__device__ __half g_y1h[(size_t)4 * NN * HH];        // layer1 basis products (51.2 MB, L2-resident)
__device__ float g_z2[(size_t)4 * NN * CC];
__device__ __nv_bfloat16 g_w1thi[5 * 128 * 128];
__device__ __nv_bfloat16 g_w1tlo[5 * 128 * 128];
__device__ __half g_w1tf[4 * 128 * 128];
// CSR (built once per call); edge record = {src|rel<<16 (or sid|rel<<16), norm bits}
__device__ int g_deg[NN];
__device__ int g_cur[NN];
__device__ int g_off[NN + 1];
__device__ uint2 g_rec0[EE];                         // (h[src] | rel<<16, norm)
__device__ uint2 g_rec1[EE];                         // (src | rel<<16, norm)

// ---------------- helpers ----------------
__device__ __forceinline__ uint32_t pack_bf16(float a, float b) {
    __nv_bfloat162 t = __floats2bfloat162_rn(a, b);
    return *(uint32_t*)&t;
}
__device__ __forceinline__ uint32_t pack_f16(float a, float b) {
    __half2 t = __floats2half2_rn(a, b);
    return *(uint32_t*)&t;
}
__device__ __forceinline__ uint32_t smem_u32(const void* p) {
    uint32_t a;
    asm("{ .reg .u64 t; cvta.to.shared.u64 t, %1; cvt.u32.u64 %0, t; }" : "=r"(a) : "l"(p));
    return a;
}
#define MMA16816BF(c, a0, a1, a2, a3, b0, b1)                                 \
    asm volatile("mma.sync.aligned.m16n8k16.row.col.f32.bf16.bf16.f32 "       \
                 "{%0,%1,%2,%3}, {%4,%5,%6,%7}, {%8,%9}, {%0,%1,%2,%3};"      \
                 : "+f"((c)[0]), "+f"((c)[1]), "+f"((c)[2]), "+f"((c)[3])     \
                 : "r"(a0), "r"(a1), "r"(a2), "r"(a3), "r"(b0), "r"(b1))
#define MMA16816F(c, a0, a1, a2, a3, b0, b1)                                  \
    asm volatile("mma.sync.aligned.m16n8k16.row.col.f32.f16.f16.f32 "         \
                 "{%0,%1,%2,%3}, {%4,%5,%6,%7}, {%8,%9}, {%0,%1,%2,%3};"      \
                 : "+f"((c)[0]), "+f"((c)[1]), "+f"((c)[2]), "+f"((c)[3])     \
                 : "r"(a0), "r"(a1), "r"(a2), "r"(a3), "r"(b0), "r"(b1))
#define LDSM4(r, addr)                                                        \
    asm volatile("ldmatrix.sync.aligned.m8n8.x4.shared.b16 {%0,%1,%2,%3}, [%4];" \
                 : "=r"((r)[0]), "=r"((r)[1]), "=r"((r)[2]), "=r"((r)[3])     \
                 : "r"(addr))

#define LSTRIDE 136
#define AH_OFF 0
#define AL_OFF 17408
#define WH_OFF 34816
#define WL_OFF 69632
#define SMEM_X1 104448
#define FA_OFF 0
#define FW_OFF 17408
#define SMEM_F16 52224

// ================= CSR build =================
__global__ void zero_k(int* deg, int* cur) {
    int i = blockIdx.x * 256 + threadIdx.x;
    if (i < NN) { deg[i] = 0; cur[i] = 0; }
}
__global__ void hist_k(const int* __restrict__ dst, int* __restrict__ deg) {
    int e = blockIdx.x * 256 + threadIdx.x;
    if (e < EE) atomicAdd(&deg[__ldg(&dst[e])], 1);
}
__global__ void scan_k(const int* __restrict__ deg, int* __restrict__ off) {
    __shared__ int bs[1024];
    const int t = threadIdx.x;
    const int CH = (NN + 1023) / 1024;
    int base0 = t * CH;
    int s = 0;
    for (int j = 0; j < CH; j++) {
        int idx = base0 + j;
        if (idx < NN) s += deg[idx];
    }
    bs[t] = s;
    __syncthreads();
    for (int o = 1; o < 1024; o <<= 1) {
        int tmp = (t >= o) ? bs[t - o] : 0;
        __syncthreads();
        bs[t] += tmp;
        __syncthreads();
    }
    int run = bs[t] - s;
    for (int j = 0; j < CH; j++) {
        int idx = base0 + j;
        if (idx < NN) { off[idx] = run; run += deg[idx]; }
    }
    if (t == 1023) off[NN] = bs[1023];
}
__global__ void fill_k(const int* __restrict__ src, const int* __restrict__ dst,
                       const int* __restrict__ h, const int* __restrict__ rel,
                       const float* __restrict__ norm,
                       const int* __restrict__ off, int* __restrict__ cur,
                       uint2* __restrict__ rec0, uint2* __restrict__ rec1) {
    int e = blockIdx.x * 256 + threadIdx.x;
    if (e >= EE) return;
    int s = __ldg(&src[e]);
    int d = __ldg(&dst[e]);
    uint32_t rr = (uint32_t)__ldg(&rel[e]);
    uint32_t nb = __float_as_uint(__ldg(&norm[e]));
    int pos = atomicAdd(&cur[d], 1);
    int idx = __ldg(&off[d]) + pos;
    uint32_t sid = (uint32_t)__ldg(&h[s]);
    rec0[idx] = make_uint2(sid | (rr << 16), nb);
    rec1[idx] = make_uint2((uint32_t)s | (rr << 16), nb);
}

// ================= prep =================
__global__ void prep_w1t(const float* __restrict__ bases1, const float* __restrict__ loop1,
                         __nv_bfloat16* __restrict__ whi, __nv_bfloat16* __restrict__ wlo,
                         __half* __restrict__ wf) {
    int i = blockIdx.x * 256 + threadIdx.x;
    if (i >= 5 * 16384) return;
    int s = i >> 14;
    int f = (i >> 7) & 127;
    int d = i & 127;
    float v = (s < 4) ? __ldg(&bases1[s * 16384 + d * 128 + f]) : __ldg(&loop1[d * 128 + f]);
    __nv_bfloat16 hi = __float2bfloat16(v);
    __nv_bfloat16 lo = __float2bfloat16(v - __bfloat162float(hi));
    whi[i] = hi;
    wlo[i] = lo;
    if (s < 4) wf[i] = __float2half(v);
}

__global__ void compose0_k(const float* __restrict__ b0, const float* __restrict__ wc,
                           __half* __restrict__ T0) {
    int i = blockIdx.x * 256 + threadIdx.x;
    if (i >= NN * 32) return;
    const float4* bp = (const float4*)b0;
    const long PS = (long)NN * 32;
    float4 v0 = __ldg(bp + i);
    float4 v1 = __ldg(bp + i + PS);
    float4 v2 = __ldg(bp + i + 2 * PS);
    float4 v3 = __ldg(bp + i + 3 * PS);
    uint2* tp = (uint2*)T0;
#pragma unroll
    for (int r = 0; r < RR; r++) {
        float c0 = __ldg(&wc[r * 4 + 0]), c1 = __ldg(&wc[r * 4 + 1]);
        float c2 = __ldg(&wc[r * 4 + 2]), c3 = __ldg(&wc[r * 4 + 3]);
        float mx = c0 * v0.x + c1 * v1.x + c2 * v2.x + c3 * v3.x;
        float my = c0 * v0.y + c1 * v1.y + c2 * v2.y + c3 * v3.y;
        float mz = c0 * v0.z + c1 * v1.z + c2 * v2.z + c3 * v3.z;
        float mw = c0 * v0.w + c1 * v1.w + c2 * v2.w + c3 * v3.w;
        uint2 u = { pack_f16(mx, my), pack_f16(mz, mw) };
        tp[(size_t)r * PS + i] = u;
    }
}

__global__ void compose2_k(const float* __restrict__ Z, const float* __restrict__ wc,
                           __half* __restrict__ T2) {
    int i = blockIdx.x * 256 + threadIdx.x;
    if (i >= NN * 4) return;
    const float4* zp = (const float4*)Z;
    const long PS = (long)NN * 4;
    float4 v0 = __ldg(zp + i);
    float4 v1 = __ldg(zp + i + PS);
    float4 v2 = __ldg(zp + i + 2 * PS);
    float4 v3 = __ldg(zp + i + 3 * PS);
    uint2* tp = (uint2*)T2;
#pragma unroll
    for (int r = 0; r < RR; r++) {
        float c0 = __ldg(&wc[r * 4 + 0]), c1 = __ldg(&wc[r * 4 + 1]);
        float c2 = __ldg(&wc[r * 4 + 2]), c3 = __ldg(&wc[r * 4 + 3]);
        float mx = c0 * v0.x + c1 * v1.x + c2 * v2.x + c3 * v3.x;
        float my = c0 * v0.y + c1 * v1.y + c2 * v2.y + c3 * v3.y;
        float mz = c0 * v0.z + c1 * v1.z + c2 * v2.z + c3 * v3.z;
        float mw = c0 * v0.w + c1 * v1.w + c2 * v2.w + c3 * v3.w;
        uint2 u = { pack_f16(mx, my), pack_f16(mz, mw) };
        tp[(size_t)r * PS + i] = u;
    }
}

// ---------------- layer 0 init ----------------
__global__ void init0_k(const int* __restrict__ h, const float* __restrict__ loop0,
                        const float* __restrict__ bias0, float* __restrict__ out) {
    int i = blockIdx.x * 256 + threadIdx.x;
    if (i >= NN * HH) return;
    int n = i >> 7;
    int f = i & 127;
    int id = __ldg(&h[n]);
    out[i] = __ldg(&loop0[(size_t)id * HH + f]) + __ldg(&bias0[f]);
}

// ================= aggregators (owner-computes; no atomics) =================
// Layer 0: warp/node, single composed-row gather from T0, 4-edge unrolled.
__global__ void __launch_bounds__(256) aggT_k(
    const int* __restrict__ off, const uint2* __restrict__ rec,
    const __half* __restrict__ T, float* __restrict__ out) {
    int d = blockIdx.x * 8 + (threadIdx.x >> 5);
    if (d >= NN) return;
    int lane = threadIdx.x & 31;
    int beg = __ldg(&off[d]);
    int end = __ldg(&off[d + 1]);
    if (beg == end) return;
    const uint2* tp = (const uint2*)T;
    float4 acc = {0.f, 0.f, 0.f, 0.f};
    int i = beg;
    for (; i + 3 < end; i += 4) {
        uint2 e0 = __ldg(&rec[i]),     e1 = __ldg(&rec[i + 1]);
        uint2 e2 = __ldg(&rec[i + 2]), e3 = __ldg(&rec[i + 3]);
        size_t r0 = (size_t)(e0.x >> 16) * NN + (e0.x & 0xFFFFu);
        size_t r1 = (size_t)(e1.x >> 16) * NN + (e1.x & 0xFFFFu);
        size_t r2 = (size_t)(e2.x >> 16) * NN + (e2.x & 0xFFFFu);
        size_t r3 = (size_t)(e3.x >> 16) * NN + (e3.x & 0xFFFFu);
        uint2 u0 = __ldg(tp + r0 * 32 + lane);
        uint2 u1 = __ldg(tp + r1 * 32 + lane);
        uint2 u2 = __ldg(tp + r2 * 32 + lane);
        uint2 u3 = __ldg(tp + r3 * 32 + lane);
        float n0 = __uint_as_float(e0.y), n1 = __uint_as_float(e1.y);
        float n2 = __uint_as_float(e2.y), n3 = __uint_as_float(e3.y);
        float2 a0 = __half22float2(*(const __half2*)&u0.x), b0 = __half22float2(*(const __half2*)&u0.y);
        float2 a1 = __half22float2(*(const __half2*)&u1.x), b1 = __half22float2(*(const __half2*)&u1.y);
        float2 a2 = __half22float2(*(const __half2*)&u2.x), b2 = __half22float2(*(const __half2*)&u2.y);
        float2 a3 = __half22float2(*(const __half2*)&u3.x), b3 = __half22float2(*(const __half2*)&u3.y);
        acc.x += a0.x * n0 + a1.x * n1 + a2.x * n2 + a3.x * n3;
        acc.y += a0.y * n0 + a1.y * n1 + a2.y * n2 + a3.y * n3;
        acc.z += b0.x * n0 + b1.x * n1 + b2.x * n2 + b3.x * n3;
        acc.w += b0.y * n0 + b1.y * n1 + b2.y * n2 + b3.y * n3;
    }
    for (; i < end; i++) {
        uint2 e0 = __ldg(&rec[i]);
        size_t r0 = (size_t)(e0.x >> 16) * NN + (e0.x & 0xFFFFu);
        uint2 u0 = __ldg(tp + r0 * 32 + lane);
        float n0 = __uint_as_float(e0.y);
        float2 a0 = __half22float2(*(const __half2*)&u0.x), b0 = __half22float2(*(const __half2*)&u0.y);
        acc.x += a0.x * n0; acc.y += a0.y * n0;
        acc.z += b0.x * n0; acc.w += b0.y * n0;
    }
    float4* op = (float4*)(out + (long)d * HH) + lane;
    float4 cur = *op;
    cur.x += acc.x; cur.y += acc.y; cur.z += acc.z; cur.w += acc.w;
    *op = cur;
}

// Layer 1: warp/node, 4-basis gather from L2-resident Y (no compose/table), 2-edge unrolled.
__global__ void __launch_bounds__(256) aggY_k(
    const int* __restrict__ off, const uint2* __restrict__ rec,
    const float* __restrict__ wc, const __half* __restrict__ Yh,
    float* __restrict__ out) {
    int d = blockIdx.x * 8 + (threadIdx.x >> 5);
    if (d >= NN) return;
    int lane = threadIdx.x & 31;
    int beg = __ldg(&off[d]);
    int end = __ldg(&off[d + 1]);
    if (beg == end) return;
    const uint2* yp = (const uint2*)Yh;
    const long SS = (long)NN * 32;
    float4 acc = {0.f, 0.f, 0.f, 0.f};
    int i = beg;
    for (; i + 1 < end; i += 2) {
        uint2 e0 = __ldg(&rec[i]), e1 = __ldg(&rec[i + 1]);
        int s0 = e0.x & 0xFFFFu, rl0 = e0.x >> 16;
        int s1 = e1.x & 0xFFFFu, rl1 = e1.x >> 16;
        float nm0 = __uint_as_float(e0.y), nm1 = __uint_as_float(e1.y);
        long ba0 = (long)s0 * 32 + lane, ba1 = (long)s1 * 32 + lane;
        uint2 p0 = __ldg(yp + ba0),          q0 = __ldg(yp + ba1);
        uint2 p1 = __ldg(yp + ba0 + SS),     q1 = __ldg(yp + ba1 + SS);
        uint2 p2 = __ldg(yp + ba0 + 2 * SS), q2 = __ldg(yp + ba1 + 2 * SS);
        uint2 p3 = __ldg(yp + ba0 + 3 * SS), q3 = __ldg(yp + ba1 + 3 * SS);
        float c00 = nm0 * __ldg(&wc[rl0 * 4 + 0]), c01 = nm0 * __ldg(&wc[rl0 * 4 + 1]);
        float c02 = nm0 * __ldg(&wc[rl0 * 4 + 2]), c03 = nm0 * __ldg(&wc[rl0 * 4 + 3]);
        float c10 = nm1 * __ldg(&wc[rl1 * 4 + 0]), c11 = nm1 * __ldg(&wc[rl1 * 4 + 1]);
        float c12 = nm1 * __ldg(&wc[rl1 * 4 + 2]), c13 = nm1 * __ldg(&wc[rl1 * 4 + 3]);
        float2 pa0 = __half22float2(*(const __half2*)&p0.x), pb0 = __half22float2(*(const __half2*)&p0.y);
        float2 pa1 = __half22float2(*(const __half2*)&p1.x), pb1 = __half22float2(*(const __half2*)&p1.y);
        float2 pa2 = __half22float2(*(const __half2*)&p2.x), pb2 = __half22float2(*(const __half2*)&p2.y);
        float2 pa3 = __half22float2(*(const __half2*)&p3.x), pb3 = __half22float2(*(const __half2*)&p3.y);
        acc.x += c00 * pa0.x + c01 * pa1.x + c02 * pa2.x + c03 * pa3.x;
        acc.y += c00 * pa0.y + c01 * pa1.y + c02 * pa2.y + c03 * pa3.y;
        acc.z += c00 * pb0.x + c01 * pb1.x + c02 * pb2.x + c03 * pb3.x;
        acc.w += c00 * pb0.y + c01 * pb1.y + c02 * pb2.y + c03 * pb3.y;
        float2 qa0 = __half22float2(*(const __half2*)&q0.x), qb0 = __half22float2(*(const __half2*)&q0.y);
        float2 qa1 = __half22float2(*(const __half2*)&q1.x), qb1 = __half22float2(*(const __half2*)&q1.y);
        float2 qa2 = __half22float2(*(const __half2*)&q2.x), qb2 = __half22float2(*(const __half2*)&q2.y);
        float2 qa3 = __half22float2(*(const __half2*)&q3.x), qb3 = __half22float2(*(const __half2*)&q3.y);
        acc.x += c10 * qa0.x + c11 * qa1.x + c12 * qa2.x + c13 * qa3.x;
        acc.y += c10 * qa0.y + c11 * qa1.y + c12 * qa2.y + c13 * qa3.y;
        acc.z += c10 * qb0.x + c11 * qb1.x + c12 * qb2.x + c13 * qb3.x;
        acc.w += c10 * qb0.y + c11 * qb1.y + c12 * qb2.y + c13 * qb3.y;
    }
    if (i < end) {
        uint2 e0 = __ldg(&rec[i]);
        int s0 = e0.x & 0xFFFFu, rl0 = e0.x >> 16;
        float nm0 = __uint_as_float(e0.y);
        long ba0 = (long)s0 * 32 + lane;
        uint2 p0 = __ldg(yp + ba0);
        uint2 p1 = __ldg(yp + ba0 + SS);
        uint2 p2 = __ldg(yp + ba0 + 2 * SS);
        uint2 p3 = __ldg(yp + ba0 + 3 * SS);
        float c00 = nm0 * __ldg(&wc[rl0 * 4 + 0]), c01 = nm0 * __ldg(&wc[rl0 * 4 + 1]);
        float c02 = nm0 * __ldg(&wc[rl0 * 4 + 2]), c03 = nm0 * __ldg(&wc[rl0 * 4 + 3]);
        float2 pa0 = __half22float2(*(const __half2*)&p0.x), pb0 = __half22float2(*(const __half2*)&p0.y);
        float2 pa1 = __half22float2(*(const __half2*)&p1.x), pb1 = __half22float2(*(const __half2*)&p1.y);
        float2 pa2 = __half22float2(*(const __half2*)&p2.x), pb2 = __half22float2(*(const __half2*)&p2.y);
        float2 pa3 = __half22float2(*(const __half2*)&p3.x), pb3 = __half22float2(*(const __half2*)&p3.y);
        acc.x += c00 * pa0.x + c01 * pa1.x + c02 * pa2.x + c03 * pa3.x;
        acc.y += c00 * pa0.y + c01 * pa1.y + c02 * pa2.y + c03 * pa3.y;
        acc.z += c00 * pb0.x + c01 * pb1.x + c02 * pb2.x + c03 * pb3.x;
        acc.w += c00 * pb0.y + c01 * pb1.y + c02 * pb2.y + c03 * pb3.y;
    }
    float4* op = (float4*)(out + (long)d * HH) + lane;
    float4 cur = *op;
    cur.x += acc.x; cur.y += acc.y; cur.z += acc.z; cur.w += acc.w;
    *op = cur;
}

// Layer 2: 4 threads/node, T2 gather, 4-edge unrolled.
__global__ void __launch_bounds__(256) agg2_k(
    const int* __restrict__ off, const uint2* __restrict__ rec,
    const __half* __restrict__ T2, float* __restrict__ out) {
    int tid = blockIdx.x * 256 + threadIdx.x;
    int d = tid >> 2;
    if (d >= NN) return;
    int q = tid & 3;
    int beg = __ldg(&off[d]);
    int end = __ldg(&off[d + 1]);
    if (beg == end) return;
    const uint2* tp = (const uint2*)T2;
    float4 acc = {0.f, 0.f, 0.f, 0.f};
    int i = beg;
    for (; i + 3 < end; i += 4) {
        uint2 e0 = __ldg(&rec[i]),     e1 = __ldg(&rec[i + 1]);
        uint2 e2 = __ldg(&rec[i + 2]), e3 = __ldg(&rec[i + 3]);
        size_t r0 = (size_t)(e0.x >> 16) * NN + (e0.x & 0xFFFFu);
        size_t r1 = (size_t)(e1.x >> 16) * NN + (e1.x & 0xFFFFu);
        size_t r2 = (size_t)(e2.x >> 16) * NN + (e2.x & 0xFFFFu);
        size_t r3 = (size_t)(e3.x >> 16) * NN + (e3.x & 0xFFFFu);
        uint2 u0 = __ldg(tp + r0 * 4 + q);
        uint2 u1 = __ldg(tp + r1 * 4 + q);
        uint2 u2 = __ldg(tp + r2 * 4 + q);
        uint2 u3 = __ldg(tp + r3 * 4 + q);
        float n0 = __uint_as_float(e0.y), n1 = __uint_as_float(e1.y);
        float n2 = __uint_as_float(e2.y), n3 = __uint_as_float(e3.y);
        float2 a0 = __half22float2(*(const __half2*)&u0.x), b0 = __half22float2(*(const __half2*)&u0.y);
        float2 a1 = __half22float2(*(const __half2*)&u1.x), b1 = __half22float2(*(const __half2*)&u1.y);
        float2 a2 = __half22float2(*(const __half2*)&u2.x), b2 = __half22float2(*(const __half2*)&u2.y);
        float2 a3 = __half22float2(*(const __half2*)&u3.x), b3 = __half22float2(*(const __half2*)&u3.y);
        acc.x += a0.x * n0 + a1.x * n1 + a2.x * n2 + a3.x * n3;
        acc.y += a0.y * n0 + a1.y * n1 + a2.y * n2 + a3.y * n3;
        acc.z += b0.x * n0 + b1.x * n1 + b2.x * n2 + b3.x * n3;
        acc.w += b0.y * n0 + b1.y * n1 + b2.y * n2 + b3.y * n3;
    }
    for (; i < end; i++) {
        uint2 e0 = __ldg(&rec[i]);
        size_t r0 = (size_t)(e0.x >> 16) * NN + (e0.x & 0xFFFFu);
        uint2 u0 = __ldg(tp + r0 * 4 + q);
        float n0 = __uint_as_float(e0.y);
        float2 a0 = __half22float2(*(const __half2*)&u0.x), b0 = __half22float2(*(const __half2*)&u0.y);
        acc.x += a0.x * n0; acc.y += a0.y * n0;
        acc.z += b0.x * n0; acc.w += b0.y * n0;
    }
    float4* op = (float4*)(out + (long)d * CC) + q;
    float4 cur = *op;
    cur.x += acc.x; cur.y += acc.y; cur.z += acc.z; cur.w += acc.w;
    *op = cur;
}

// ---------------- fp16 HMMA: Y_b = relu(x0) @ B1_b ----------------
__global__ void __launch_bounds__(256, 3) mma_f16(
    const float* __restrict__ X, const __half* __restrict__ Wf,
    __half* __restrict__ Yh) {
    extern __shared__ char sm[];
    const int tid = threadIdx.x;
    const int w = tid >> 5;
    const int lane = tid & 31;
    const int slice = blockIdx.y;
    const int row0 = blockIdx.x * 64;
    {
        const uint2* g = (const uint2*)(Wf + slice * 16384);
#pragma unroll
        for (int i = 0; i < 16; i++) {
            int r = w * 16 + i;
            uint2 v = __ldg(g + r * 32 + lane);
            *(uint2*)(sm + FW_OFF + r * (LSTRIDE * 2) + lane * 8) = v;
        }
    }
    {
#pragma unroll
        for (int i = 0; i < 8; i++) {
            int r = w * 8 + i;
            int rg = row0 + r;
            float4 q = (rg < NN) ? __ldg((const float4*)X + (long)rg * 32 + lane)
                                 : make_float4(0.f, 0.f, 0.f, 0.f);
            uint2 u = { pack_f16(fmaxf(q.x, 0.f), fmaxf(q.y, 0.f)),
                        pack_f16(fmaxf(q.z, 0.f), fmaxf(q.w, 0.f)) };
            *(uint2*)(sm + FA_OFF + r * (LSTRIDE * 2) + lane * 8) = u;
        }
    }
    __syncthreads();

    const int wm = w & 1, wn = w >> 1;
    const int r0 = wm * 32, c0 = wn * 32;
    const uint32_t lrow = lane & 15;
    const uint32_t lkh = (lane >> 4) << 3;
    const uint32_t sA = smem_u32(sm + FA_OFF), sW = smem_u32(sm + FW_OFF);

    float acc[2][4][4];
#pragma unroll
    for (int mi = 0; mi < 2; mi++)
#pragma unroll
        for (int j = 0; j < 4; j++)
            acc[mi][j][0] = acc[mi][j][1] = acc[mi][j][2] = acc[mi][j][3] = 0.f;

#pragma unroll
    for (int ks = 0; ks < 8; ks++) {
        const uint32_t kb = ks * 16 + lkh;
        uint32_t A[2][4], B[2][4];
#pragma unroll
        for (int mi = 0; mi < 2; mi++)
            LDSM4(A[mi], sA + ((r0 + mi * 16 + lrow) * LSTRIDE + kb) * 2);
#pragma unroll
        for (int nj = 0; nj < 2; nj++)
            LDSM4(B[nj], sW + ((c0 + nj * 16 + lrow) * LSTRIDE + kb) * 2);
#pragma unroll
        for (int mi = 0; mi < 2; mi++)
#pragma unroll
            for (int nj = 0; nj < 2; nj++) {
                MMA16816F(acc[mi][nj * 2],     A[mi][0], A[mi][1], A[mi][2], A[mi][3], B[nj][0], B[nj][2]);
                MMA16816F(acc[mi][nj * 2 + 1], A[mi][0], A[mi][1], A[mi][2], A[mi][3], B[nj][1], B[nj][3]);
            }
    }

    __half* O = Yh + (size_t)slice * NN * HH;
    const int g = lane >> 2, tg = lane & 3;
#pragma unroll
    for (int mi = 0; mi < 2; mi++) {
        long ra = row0 + r0 + mi * 16 + g;
        long rb = ra + 8;
#pragma unroll
        for (int j = 0; j < 4; j++) {
            int col = c0 + j * 8 + tg * 2;
            if (ra < NN) *(uint32_t*)(O + ra * 128 + col) = pack_f16(acc[mi][j][0], acc[mi][j][1]);
            if (rb < NN) *(uint32_t*)(O + rb * 128 + col) = pack_f16(acc[mi][j][2], acc[mi][j][3]);
        }
    }
}

// ---------------- bf16 hi/lo HMMA: x1 = relu(x0) @ loop1 + bias1 ----------------
__global__ void __launch_bounds__(256, 2) mma_x1(
    const float* __restrict__ X,
    const __nv_bfloat16* __restrict__ Wth, const __nv_bfloat16* __restrict__ Wtl,
    float* __restrict__ x1, const float* __restrict__ bias1) {
    extern __shared__ char sm[];
    const int tid = threadIdx.x;
    const int w = tid >> 5;
    const int lane = tid & 31;
    const int row0 = blockIdx.x * 64;
    {
        const uint2* gh = (const uint2*)(Wth + 4 * 16384);
        const uint2* gl = (const uint2*)(Wtl + 4 * 16384);
#pragma unroll
        for (int i = 0; i < 16; i++) {
            int r = w * 16 + i;
            uint2 vh = __ldg(gh + r * 32 + lane);
            uint2 vl = __ldg(gl + r * 32 + lane);
            *(uint2*)(sm + WH_OFF + r * (LSTRIDE * 2) + lane * 8) = vh;
            *(uint2*)(sm + WL_OFF + r * (LSTRIDE * 2) + lane * 8) = vl;
        }
    }
    {
#pragma unroll
        for (int i = 0; i < 8; i++) {
            int r = w * 8 + i;
            int rg = row0 + r;
            float4 q = (rg < NN) ? __ldg((const float4*)X + (long)rg * 32 + lane)
                                 : make_float4(0.f, 0.f, 0.f, 0.f);
            q.x = fmaxf(q.x, 0.f); q.y = fmaxf(q.y, 0.f);
            q.z = fmaxf(q.z, 0.f); q.w = fmaxf(q.w, 0.f);
            float hx = __bfloat162float(__float2bfloat16(q.x));
            float hy = __bfloat162float(__float2bfloat16(q.y));
            float hz = __bfloat162float(__float2bfloat16(q.z));
            float hw = __bfloat162float(__float2bfloat16(q.w));
            uint2 uh = { pack_bf16(q.x, q.y), pack_bf16(q.z, q.w) };
            uint2 ul = { pack_bf16(q.x - hx, q.y - hy), pack_bf16(q.z - hz, q.w - hw) };
            *(uint2*)(sm + AH_OFF + r * (LSTRIDE * 2) + lane * 8) = uh;
            *(uint2*)(sm + AL_OFF + r * (LSTRIDE * 2) + lane * 8) = ul;
        }
    }
    __syncthreads();

    const int wm = w & 1, wn = w >> 1;
    const int r0 = wm * 32, c0 = wn * 32;
    const uint32_t lrow = lane & 15;
    const uint32_t lkh = (lane >> 4) << 3;
    const uint32_t sAH = smem_u32(sm + AH_OFF), sAL = smem_u32(sm + AL_OFF);
    const uint32_t sWH = smem_u32(sm + WH_OFF), sWL = smem_u32(sm + WL_OFF);

    float acc[2][4][4];
#pragma unroll
    for (int mi = 0; mi < 2; mi++)
#pragma unroll
        for (int j = 0; j < 4; j++)
            acc[mi][j][0] = acc[mi][j][1] = acc[mi][j][2] = acc[mi][j][3] = 0.f;

#pragma unroll
    for (int ks = 0; ks < 8; ks++) {
        const uint32_t kb = ks * 16 + lkh;
        uint32_t AH[2][4], AL[2][4], BH[2][4], BL[2][4];
#pragma unroll
        for (int mi = 0; mi < 2; mi++) {
            uint32_t off = ((r0 + mi * 16 + lrow) * LSTRIDE + kb) * 2;
            LDSM4(AH[mi], sAH + off);
            LDSM4(AL[mi], sAL + off);
        }
#pragma unroll
        for (int nj = 0; nj < 2; nj++) {
            uint32_t off = ((c0 + nj * 16 + lrow) * LSTRIDE + kb) * 2;
            LDSM4(BH[nj], sWH + off);
            LDSM4(BL[nj], sWL + off);
        }
#pragma unroll
        for (int mi = 0; mi < 2; mi++)
#pragma unroll
            for (int nj = 0; nj < 2; nj++) {
                float* cA = acc[mi][nj * 2];
                float* cB = acc[mi][nj * 2 + 1];
                MMA16816BF(cA, AH[mi][0], AH[mi][1], AH[mi][2], AH[mi][3], BH[nj][0], BH[nj][2]);
                MMA16816BF(cA, AH[mi][0], AH[mi][1], AH[mi][2], AH[mi][3], BL[nj][0], BL[nj][2]);
                MMA16816BF(cA, AL[mi][0], AL[mi][1], AL[mi][2], AL[mi][3], BH[nj][0], BH[nj][2]);
                MMA16816BF(cB, AH[mi][0], AH[mi][1], AH[mi][2], AH[mi][3], BH[nj][1], BH[nj][3]);
                MMA16816BF(cB, AH[mi][0], AH[mi][1], AH[mi][2], AH[mi][3], BL[nj][1], BL[nj][3]);
                MMA16816BF(cB, AL[mi][0], AL[mi][1], AL[mi][2], AL[mi][3], BH[nj][1], BH[nj][3]);
            }
    }

    const int g = lane >> 2, tg = lane & 3;
#pragma unroll
    for (int mi = 0; mi < 2; mi++) {
        long ra = row0 + r0 + mi * 16 + g;
        long rb = ra + 8;
#pragma unroll
        for (int j = 0; j < 4; j++) {
            int col = c0 + j * 8 + tg * 2;
            float b0 = __ldg(&bias1[col]), b1 = __ldg(&bias1[col + 1]);
            if (ra < NN) {
                float2 v = { acc[mi][j][0] + b0, acc[mi][j][1] + b1 };
                *(float2*)(x1 + ra * 128 + col) = v;
            }
            if (rb < NN) {
                float2 v = { acc[mi][j][2] + b0, acc[mi][j][3] + b1 };
                *(float2*)(x1 + rb * 128 + col) = v;
            }
        }
    }
}

// ---------------- layer 2 transform, F=16; mode 0: bases->Z (grid.y=4), mode 1: loop->out+bias ----------------
__global__ void __launch_bounds__(128) transform16(
    const float* __restrict__ X, const float* __restrict__ bases2,
    const float* __restrict__ loop2, const float* __restrict__ bias2,
    float* __restrict__ Z, float* __restrict__ out, int mode) {
    __shared__ float ws[128 * 16];
    __shared__ float xs[64][129];
    const int y = blockIdx.y;
    const float* W = (mode == 0) ? (bases2 + y * 2048) : loop2;
    float* O = (mode == 0) ? (Z + (long)y * NN * CC) : out;
    const int t = threadIdx.x;
    const int col = t & 15, rg = t >> 4;
    const int row0 = blockIdx.x * 64;
    for (int i = t; i < 128 * 16; i += 128) ws[i] = __ldg(&W[i]);
#pragma unroll 4
    for (int i = 0; i < 64; i++) {
        int rr = row0 + i;
        float v = (rr < NN) ? __ldg(&X[(long)rr * 128 + t]) : 0.f;
        xs[i][t] = fmaxf(v, 0.f);
    }
    __syncthreads();
    const float bv = (mode == 1) ? __ldg(&bias2[col]) : 0.f;
    for (int p = 0; p < 8; p++) {
        int rl = p * 8 + rg;
        float a = 0.f;
#pragma unroll 16
        for (int d = 0; d < 128; d++) a = fmaf(xs[rl][d], ws[d * 16 + col], a);
        int rr = row0 + rl;
        if (rr < NN) O[(long)rr * 16 + col] = a + bv;
    }
}

// ---------------- launch ----------------
extern "C" void kernel_launch(void* const* d_in, const int* in_sizes, int n_in,
                              void* d_out, int out_size) {
    const int*   src    = (const int*)d_in[0];
    const int*   dst    = (const int*)d_in[1];
    const int*   h      = (const int*)d_in[2];
    const int*   rtab   = (const int*)d_in[3];
    const float* norm   = (const float*)d_in[4];
    const float* bases0 = (const float*)d_in[5];
    const float* wcomp0 = (const float*)d_in[6];
    const float* loop0  = (const float*)d_in[7];
    const float* bias0  = (const float*)d_in[8];
    const float* bases1 = (const float*)d_in[9];
    const float* wcomp1 = (const float*)d_in[10];
    const float* loop1  = (const float*)d_in[11];
    const float* bias1  = (const float*)d_in[12];
    const float* bases2 = (const float*)d_in[13];
    const float* wcomp2 = (const float*)d_in[14];
    const float* loop2  = (const float*)d_in[15];
    const float* bias2  = (const float*)d_in[16];
    float* out = (float*)d_out;

    float *p_x0, *p_x1, *p_z2;
    __half *p_t0, *p_t2, *p_y1h, *p_wf;
    __nv_bfloat16 *p_whi, *p_wlo;
    int *p_deg, *p_cur, *p_off;
    uint2 *p_r0, *p_r1;
    cudaGetSymbolAddress((void**)&p_x0, g_x0);
    cudaGetSymbolAddress((void**)&p_x1, g_x1);
    cudaGetSymbolAddress((void**)&p_t0, g_t0);
    cudaGetSymbolAddress((void**)&p_t2, g_t2);
    cudaGetSymbolAddress((void**)&p_y1h, g_y1h);
    cudaGetSymbolAddress((void**)&p_z2, g_z2);
    cudaGetSymbolAddress((void**)&p_whi, g_w1thi);
    cudaGetSymbolAddress((void**)&p_wlo, g_w1tlo);
    cudaGetSymbolAddress((void**)&p_wf, g_w1tf);
    cudaGetSymbolAddress((void**)&p_deg, g_deg);
    cudaGetSymbolAddress((void**)&p_cur, g_cur);
    cudaGetSymbolAddress((void**)&p_off, g_off);
    cudaGetSymbolAddress((void**)&p_r0, g_rec0);
    cudaGetSymbolAddress((void**)&p_r1, g_rec1);

    static int init_done = 0;
    static cudaStream_t s1, s2, s3;
    static cudaEvent_t evRoot, evCmp0, evPrep, evInit, evAgg0, evX1, evAgg1, evT16b, evEnd;
    if (!init_done) {
        cudaFuncSetAttribute(mma_x1, cudaFuncAttributeMaxDynamicSharedMemorySize, SMEM_X1);
        cudaFuncSetAttribute(mma_f16, cudaFuncAttributeMaxDynamicSharedMemorySize, SMEM_F16);
        cudaStreamCreateWithFlags(&s1, cudaStreamNonBlocking);
        cudaStreamCreateWithFlags(&s2, cudaStreamNonBlocking);
        cudaStreamCreateWithFlags(&s3, cudaStreamNonBlocking);
        cudaEventCreateWithFlags(&evRoot, cudaEventDisableTiming);
        cudaEventCreateWithFlags(&evCmp0, cudaEventDisableTiming);
        cudaEventCreateWithFlags(&evPrep, cudaEventDisableTiming);
        cudaEventCreateWithFlags(&evInit, cudaEventDisableTiming);
        cudaEventCreateWithFlags(&evAgg0, cudaEventDisableTiming);
        cudaEventCreateWithFlags(&evX1, cudaEventDisableTiming);
        cudaEventCreateWithFlags(&evAgg1, cudaEventDisableTiming);
        cudaEventCreateWithFlags(&evT16b, cudaEventDisableTiming);
        cudaEventCreateWithFlags(&evEnd, cudaEventDisableTiming);
        init_done = 1;
    }

    const int nh_blocks = (NN * HH + 255) / 256;
    const int e_blocks  = (EE + 255) / 256;
    const int row_t64   = (NN + 63) / 64;
    const int ncvt      = (NN * 32 + 255) / 256;
    const int agg_blocks = (NN + 7) / 8;

    cudaEventRecord(evRoot, 0);
    cudaStreamWaitEvent(s1, evRoot, 0);
    cudaStreamWaitEvent(s2, evRoot, 0);
    cudaStreamWaitEvent(s3, evRoot, 0);

    // s3: x0 base
    init0_k<<<nh_blocks, 256, 0, s3>>>(h, loop0, bias0, p_x0);
    cudaEventRecord(evInit, s3);

    // s2: compose0, then weight images
    compose0_k<<<ncvt, 256, 0, s2>>>(bases0, wcomp0, p_t0);
    cudaEventRecord(evCmp0, s2);
    prep_w1t<<<(5 * 16384 + 255) / 256, 256, 0, s2>>>(bases1, loop1, p_whi, p_wlo, p_wf);
    cudaEventRecord(evPrep, s2);

    // s1: CSR chain
    zero_k<<<(NN + 255) / 256, 256, 0, s1>>>(p_deg, p_cur);
    hist_k<<<e_blocks, 256, 0, s1>>>(dst, p_deg);
    scan_k<<<1, 1024, 0, s1>>>(p_deg, p_off);
    fill_k<<<e_blocks, 256, 0, s1>>>(src, dst, h, rtab, norm, p_off, p_cur, p_r0, p_r1);

    // s1: layer-0 aggregate
    cudaStreamWaitEvent(s1, evCmp0, 0);
    cudaStreamWaitEvent(s1, evInit, 0);
    aggT_k<<<agg_blocks, 256, 0, s1>>>(p_off, p_r0, p_t0, p_x0);
    cudaEventRecord(evAgg0, s1);

    // s2: self-loop GEMM
    cudaStreamWaitEvent(s2, evAgg0, 0);
    mma_x1<<<row_t64, 256, SMEM_X1, s2>>>(p_x0, p_whi, p_wlo, p_x1, bias1);
    cudaEventRecord(evX1, s2);

    // s1: basis GEMMs, then 4-basis L2-resident aggregate (no compose1 / T1)
    cudaStreamWaitEvent(s1, evPrep, 0);
    mma_f16<<<dim3(row_t64, 4), 256, SMEM_F16, s1>>>(p_x0, p_wf, p_y1h);
    cudaStreamWaitEvent(s1, evX1, 0);
    aggY_k<<<agg_blocks, 256, 0, s1>>>(p_off, p_r1, wcomp1, p_y1h, p_x1);
    cudaEventRecord(evAgg1, s1);

    // s2: layer-2 self-loop -> out
    cudaStreamWaitEvent(s2, evAgg1, 0);
    transform16<<<dim3(row_t64, 1), 128, 0, s2>>>(p_x1, bases2, loop2, bias2, p_z2, out, 1);
    cudaEventRecord(evT16b, s2);

    // s1: layer-2 basis path
    transform16<<<dim3(row_t64, 4), 128, 0, s1>>>(p_x1, bases2, loop2, bias2, p_z2, out, 0);
    compose2_k<<<(NN * 4 + 255) / 256, 256, 0, s1>>>(p_z2, wcomp2, p_t2);
    cudaStreamWaitEvent(s1, evT16b, 0);
    agg2_k<<<(NN * 4 + 255) / 256, 256, 0, s1>>>(p_off, p_r1, p_t2, out);
    cudaEventRecord(evEnd, s1);

    cudaStreamWaitEvent(0, evEnd, 0);
}

// round 17
// speedup vs baseline: 1.2939x; 1.0472x over previous
#include <cuda_runtime.h>
#include <cuda_bf16.h>
#include <cuda_fp16.h>
#include <cstdint>

#define NN 50000
#define HH 128
#define CC 16
#define RR 8
#define BB 4
#define EE 800000

// ---------------- scratch (device globals; no allocations) ----------------
__device__ float g_x0[(size_t)NN * HH];
__device__ float g_x1[(size_t)NN * HH];
__device__ __half g_t0[(size_t)RR * NN * HH];        // composed layer0 tables (102.4 MB)
__device__ __half g_t2[(size_t)RR * NN * CC];        // composed layer2 tables (12.8 MB)
__device__ __half g_y1h[(size_t)4 * NN * HH];        // layer1 basis products (51.2 MB, L2-resident)
__device__ float g_z2[(size_t)4 * NN * CC];
__device__ __nv_bfloat16 g_w1thi[5 * 128 * 128];
__device__ __nv_bfloat16 g_w1tlo[5 * 128 * 128];
__device__ __half g_w1tf[4 * 128 * 128];
// CSR (built once per call); edge record = {src | rel<<16, norm bits}
__device__ int g_deg[NN];
__device__ int g_cur[NN];
__device__ int g_off[NN + 1];
__device__ uint2 g_rec[EE];

// ---------------- helpers ----------------
__device__ __forceinline__ uint32_t pack_bf16(float a, float b) {
    __nv_bfloat162 t = __floats2bfloat162_rn(a, b);
    return *(uint32_t*)&t;
}
__device__ __forceinline__ uint32_t pack_f16(float a, float b) {
    __half2 t = __floats2half2_rn(a, b);
    return *(uint32_t*)&t;
}
__device__ __forceinline__ uint32_t smem_u32(const void* p) {
    uint32_t a;
    asm("{ .reg .u64 t; cvta.to.shared.u64 t, %1; cvt.u32.u64 %0, t; }" : "=r"(a) : "l"(p));
    return a;
}
#define MMA16816BF(c, a0, a1, a2, a3, b0, b1)                                 \
    asm volatile("mma.sync.aligned.m16n8k16.row.col.f32.bf16.bf16.f32 "       \
                 "{%0,%1,%2,%3}, {%4,%5,%6,%7}, {%8,%9}, {%0,%1,%2,%3};"      \
                 : "+f"((c)[0]), "+f"((c)[1]), "+f"((c)[2]), "+f"((c)[3])     \
                 : "r"(a0), "r"(a1), "r"(a2), "r"(a3), "r"(b0), "r"(b1))
#define MMA16816F(c, a0, a1, a2, a3, b0, b1)                                  \
    asm volatile("mma.sync.aligned.m16n8k16.row.col.f32.f16.f16.f32 "         \
                 "{%0,%1,%2,%3}, {%4,%5,%6,%7}, {%8,%9}, {%0,%1,%2,%3};"      \
                 : "+f"((c)[0]), "+f"((c)[1]), "+f"((c)[2]), "+f"((c)[3])     \
                 : "r"(a0), "r"(a1), "r"(a2), "r"(a3), "r"(b0), "r"(b1))
#define LDSM4(r, addr)                                                        \
    asm volatile("ldmatrix.sync.aligned.m8n8.x4.shared.b16 {%0,%1,%2,%3}, [%4];" \
                 : "=r"((r)[0]), "=r"((r)[1]), "=r"((r)[2]), "=r"((r)[3])     \
                 : "r"(addr))

#define LSTRIDE 136
#define AH_OFF 0
#define AL_OFF 17408
#define WH_OFF 34816
#define WL_OFF 69632
#define SMEM_X1 104448
#define FA_OFF 0
#define FW_OFF 17408
#define SMEM_F16 52224

// ================= CSR build =================
__global__ void hist_k(const int* __restrict__ dst, int* __restrict__ deg) {
    int e = blockIdx.x * 256 + threadIdx.x;
    if (e < EE) atomicAdd(&deg[__ldg(&dst[e])], 1);
}
__global__ void scan_k(const int* __restrict__ deg, int* __restrict__ off) {
    __shared__ int bs[1024];
    const int t = threadIdx.x;
    const int CH = (NN + 1023) / 1024;
    int base0 = t * CH;
    int s = 0;
    for (int j = 0; j < CH; j++) {
        int idx = base0 + j;
        if (idx < NN) s += deg[idx];
    }
    bs[t] = s;
    __syncthreads();
    for (int o = 1; o < 1024; o <<= 1) {
        int tmp = (t >= o) ? bs[t - o] : 0;
        __syncthreads();
        bs[t] += tmp;
        __syncthreads();
    }
    int run = bs[t] - s;
    for (int j = 0; j < CH; j++) {
        int idx = base0 + j;
        if (idx < NN) { off[idx] = run; run += deg[idx]; }
    }
    if (t == 1023) off[NN] = bs[1023];
}
__global__ void fill_k(const int* __restrict__ src, const int* __restrict__ dst,
                       const int* __restrict__ rel, const float* __restrict__ norm,
                       const int* __restrict__ off, int* __restrict__ cur,
                       uint2* __restrict__ rec) {
    int e = blockIdx.x * 256 + threadIdx.x;
    if (e >= EE) return;
    int s = __ldg(&src[e]);
    int d = __ldg(&dst[e]);
    uint32_t rr = (uint32_t)__ldg(&rel[e]);
    uint32_t nb = __float_as_uint(__ldg(&norm[e]));
    int pos = atomicAdd(&cur[d], 1);
    int idx = __ldg(&off[d]) + pos;
    rec[idx] = make_uint2((uint32_t)s | (rr << 16), nb);
}

// ================= prep =================
__global__ void prep_w1t(const float* __restrict__ bases1, const float* __restrict__ loop1,
                         __nv_bfloat16* __restrict__ whi, __nv_bfloat16* __restrict__ wlo,
                         __half* __restrict__ wf) {
    int i = blockIdx.x * 256 + threadIdx.x;
    if (i >= 5 * 16384) return;
    int s = i >> 14;
    int f = (i >> 7) & 127;
    int d = i & 127;
    float v = (s < 4) ? __ldg(&bases1[s * 16384 + d * 128 + f]) : __ldg(&loop1[d * 128 + f]);
    __nv_bfloat16 hi = __float2bfloat16(v);
    __nv_bfloat16 lo = __float2bfloat16(v - __bfloat162float(hi));
    whi[i] = hi;
    wlo[i] = lo;
    if (s < 4) wf[i] = __float2half(v);
}

__global__ void compose0_k(const float* __restrict__ b0, const float* __restrict__ wc,
                           __half* __restrict__ T0) {
    int i = blockIdx.x * 256 + threadIdx.x;
    if (i >= NN * 32) return;
    const float4* bp = (const float4*)b0;
    const long PS = (long)NN * 32;
    float4 v0 = __ldg(bp + i);
    float4 v1 = __ldg(bp + i + PS);
    float4 v2 = __ldg(bp + i + 2 * PS);
    float4 v3 = __ldg(bp + i + 3 * PS);
    uint2* tp = (uint2*)T0;
#pragma unroll
    for (int r = 0; r < RR; r++) {
        float c0 = __ldg(&wc[r * 4 + 0]), c1 = __ldg(&wc[r * 4 + 1]);
        float c2 = __ldg(&wc[r * 4 + 2]), c3 = __ldg(&wc[r * 4 + 3]);
        float mx = c0 * v0.x + c1 * v1.x + c2 * v2.x + c3 * v3.x;
        float my = c0 * v0.y + c1 * v1.y + c2 * v2.y + c3 * v3.y;
        float mz = c0 * v0.z + c1 * v1.z + c2 * v2.z + c3 * v3.z;
        float mw = c0 * v0.w + c1 * v1.w + c2 * v2.w + c3 * v3.w;
        uint2 u = { pack_f16(mx, my), pack_f16(mz, mw) };
        tp[(size_t)r * PS + i] = u;
    }
}

__global__ void compose2_k(const float* __restrict__ Z, const float* __restrict__ wc,
                           __half* __restrict__ T2) {
    int i = blockIdx.x * 256 + threadIdx.x;
    if (i >= NN * 4) return;
    const float4* zp = (const float4*)Z;
    const long PS = (long)NN * 4;
    float4 v0 = __ldg(zp + i);
    float4 v1 = __ldg(zp + i + PS);
    float4 v2 = __ldg(zp + i + 2 * PS);
    float4 v3 = __ldg(zp + i + 3 * PS);
    uint2* tp = (uint2*)T2;
#pragma unroll
    for (int r = 0; r < RR; r++) {
        float c0 = __ldg(&wc[r * 4 + 0]), c1 = __ldg(&wc[r * 4 + 1]);
        float c2 = __ldg(&wc[r * 4 + 2]), c3 = __ldg(&wc[r * 4 + 3]);
        float mx = c0 * v0.x + c1 * v1.x + c2 * v2.x + c3 * v3.x;
        float my = c0 * v0.y + c1 * v1.y + c2 * v2.y + c3 * v3.y;
        float mz = c0 * v0.z + c1 * v1.z + c2 * v2.z + c3 * v3.z;
        float mw = c0 * v0.w + c1 * v1.w + c2 * v2.w + c3 * v3.w;
        uint2 u = { pack_f16(mx, my), pack_f16(mz, mw) };
        tp[(size_t)r * PS + i] = u;
    }
}

// ================= aggregators (owner-computes; no atomics) =================
// Layer 0 (fused init): x0[d] = loop0[h[d]] + bias0 + sum_e norm_e * T0[rel_e][h[src_e]]
__global__ void __launch_bounds__(256) aggT_k(
    const int* __restrict__ off, const uint2* __restrict__ rec,
    const int* __restrict__ h, const float* __restrict__ loop0,
    const float* __restrict__ bias0, const __half* __restrict__ T,
    float* __restrict__ out) {
    int d = blockIdx.x * 8 + (threadIdx.x >> 5);
    if (d >= NN) return;
    int lane = threadIdx.x & 31;
    int beg = __ldg(&off[d]);
    int end = __ldg(&off[d + 1]);
    const uint2* tp = (const uint2*)T;
    float4 acc = {0.f, 0.f, 0.f, 0.f};
    int i = beg;
    for (; i + 3 < end; i += 4) {
        uint2 e0 = __ldg(&rec[i]),     e1 = __ldg(&rec[i + 1]);
        uint2 e2 = __ldg(&rec[i + 2]), e3 = __ldg(&rec[i + 3]);
        // resolve node-id via h (warp-broadcast 4B loads)
        size_t r0 = (size_t)(e0.x >> 16) * NN + (uint32_t)__ldg(&h[e0.x & 0xFFFFu]);
        size_t r1 = (size_t)(e1.x >> 16) * NN + (uint32_t)__ldg(&h[e1.x & 0xFFFFu]);
        size_t r2 = (size_t)(e2.x >> 16) * NN + (uint32_t)__ldg(&h[e2.x & 0xFFFFu]);
        size_t r3 = (size_t)(e3.x >> 16) * NN + (uint32_t)__ldg(&h[e3.x & 0xFFFFu]);
        uint2 u0 = __ldg(tp + r0 * 32 + lane);
        uint2 u1 = __ldg(tp + r1 * 32 + lane);
        uint2 u2 = __ldg(tp + r2 * 32 + lane);
        uint2 u3 = __ldg(tp + r3 * 32 + lane);
        float n0 = __uint_as_float(e0.y), n1 = __uint_as_float(e1.y);
        float n2 = __uint_as_float(e2.y), n3 = __uint_as_float(e3.y);
        float2 a0 = __half22float2(*(const __half2*)&u0.x), b0 = __half22float2(*(const __half2*)&u0.y);
        float2 a1 = __half22float2(*(const __half2*)&u1.x), b1 = __half22float2(*(const __half2*)&u1.y);
        float2 a2 = __half22float2(*(const __half2*)&u2.x), b2 = __half22float2(*(const __half2*)&u2.y);
        float2 a3 = __half22float2(*(const __half2*)&u3.x), b3 = __half22float2(*(const __half2*)&u3.y);
        acc.x += a0.x * n0 + a1.x * n1 + a2.x * n2 + a3.x * n3;
        acc.y += a0.y * n0 + a1.y * n1 + a2.y * n2 + a3.y * n3;
        acc.z += b0.x * n0 + b1.x * n1 + b2.x * n2 + b3.x * n3;
        acc.w += b0.y * n0 + b1.y * n1 + b2.y * n2 + b3.y * n3;
    }
    for (; i < end; i++) {
        uint2 e0 = __ldg(&rec[i]);
        size_t r0 = (size_t)(e0.x >> 16) * NN + (uint32_t)__ldg(&h[e0.x & 0xFFFFu]);
        uint2 u0 = __ldg(tp + r0 * 32 + lane);
        float n0 = __uint_as_float(e0.y);
        float2 a0 = __half22float2(*(const __half2*)&u0.x), b0 = __half22float2(*(const __half2*)&u0.y);
        acc.x += a0.x * n0; acc.y += a0.y * n0;
        acc.z += b0.x * n0; acc.w += b0.y * n0;
    }
    // fused init: loop0[h[d]] + bias0
    int did = __ldg(&h[d]);
    float4 lv = __ldg((const float4*)loop0 + (long)did * 32 + lane);
    float4 bv = __ldg((const float4*)bias0 + lane);
    acc.x += lv.x + bv.x; acc.y += lv.y + bv.y;
    acc.z += lv.z + bv.z; acc.w += lv.w + bv.w;
    *((float4*)(out + (long)d * HH) + lane) = acc;
}

// Layer 1: warp/node, 4-basis gather from L2-resident Y, 2-edge unrolled.
__global__ void __launch_bounds__(256) aggY_k(
    const int* __restrict__ off, const uint2* __restrict__ rec,
    const float* __restrict__ wc, const __half* __restrict__ Yh,
    float* __restrict__ out) {
    int d = blockIdx.x * 8 + (threadIdx.x >> 5);
    if (d >= NN) return;
    int lane = threadIdx.x & 31;
    int beg = __ldg(&off[d]);
    int end = __ldg(&off[d + 1]);
    if (beg == end) return;
    const uint2* yp = (const uint2*)Yh;
    const long SS = (long)NN * 32;
    float4 acc = {0.f, 0.f, 0.f, 0.f};
    int i = beg;
    for (; i + 1 < end; i += 2) {
        uint2 e0 = __ldg(&rec[i]), e1 = __ldg(&rec[i + 1]);
        int s0 = e0.x & 0xFFFFu, rl0 = e0.x >> 16;
        int s1 = e1.x & 0xFFFFu, rl1 = e1.x >> 16;
        float nm0 = __uint_as_float(e0.y), nm1 = __uint_as_float(e1.y);
        long ba0 = (long)s0 * 32 + lane, ba1 = (long)s1 * 32 + lane;
        uint2 p0 = __ldg(yp + ba0),          q0 = __ldg(yp + ba1);
        uint2 p1 = __ldg(yp + ba0 + SS),     q1 = __ldg(yp + ba1 + SS);
        uint2 p2 = __ldg(yp + ba0 + 2 * SS), q2 = __ldg(yp + ba1 + 2 * SS);
        uint2 p3 = __ldg(yp + ba0 + 3 * SS), q3 = __ldg(yp + ba1 + 3 * SS);
        float c00 = nm0 * __ldg(&wc[rl0 * 4 + 0]), c01 = nm0 * __ldg(&wc[rl0 * 4 + 1]);
        float c02 = nm0 * __ldg(&wc[rl0 * 4 + 2]), c03 = nm0 * __ldg(&wc[rl0 * 4 + 3]);
        float c10 = nm1 * __ldg(&wc[rl1 * 4 + 0]), c11 = nm1 * __ldg(&wc[rl1 * 4 + 1]);
        float c12 = nm1 * __ldg(&wc[rl1 * 4 + 2]), c13 = nm1 * __ldg(&wc[rl1 * 4 + 3]);
        float2 pa0 = __half22float2(*(const __half2*)&p0.x), pb0 = __half22float2(*(const __half2*)&p0.y);
        float2 pa1 = __half22float2(*(const __half2*)&p1.x), pb1 = __half22float2(*(const __half2*)&p1.y);
        float2 pa2 = __half22float2(*(const __half2*)&p2.x), pb2 = __half22float2(*(const __half2*)&p2.y);
        float2 pa3 = __half22float2(*(const __half2*)&p3.x), pb3 = __half22float2(*(const __half2*)&p3.y);
        acc.x += c00 * pa0.x + c01 * pa1.x + c02 * pa2.x + c03 * pa3.x;
        acc.y += c00 * pa0.y + c01 * pa1.y + c02 * pa2.y + c03 * pa3.y;
        acc.z += c00 * pb0.x + c01 * pb1.x + c02 * pb2.x + c03 * pb3.x;
        acc.w += c00 * pb0.y + c01 * pb1.y + c02 * pb2.y + c03 * pb3.y;
        float2 qa0 = __half22float2(*(const __half2*)&q0.x), qb0 = __half22float2(*(const __half2*)&q0.y);
        float2 qa1 = __half22float2(*(const __half2*)&q1.x), qb1 = __half22float2(*(const __half2*)&q1.y);
        float2 qa2 = __half22float2(*(const __half2*)&q2.x), qb2 = __half22float2(*(const __half2*)&q2.y);
        float2 qa3 = __half22float2(*(const __half2*)&q3.x), qb3 = __half22float2(*(const __half2*)&q3.y);
        acc.x += c10 * qa0.x + c11 * qa1.x + c12 * qa2.x + c13 * qa3.x;
        acc.y += c10 * qa0.y + c11 * qa1.y + c12 * qa2.y + c13 * qa3.y;
        acc.z += c10 * qb0.x + c11 * qb1.x + c12 * qb2.x + c13 * qb3.x;
        acc.w += c10 * qb0.y + c11 * qb1.y + c12 * qb2.y + c13 * qb3.y;
    }
    if (i < end) {
        uint2 e0 = __ldg(&rec[i]);
        int s0 = e0.x & 0xFFFFu, rl0 = e0.x >> 16;
        float nm0 = __uint_as_float(e0.y);
        long ba0 = (long)s0 * 32 + lane;
        uint2 p0 = __ldg(yp + ba0);
        uint2 p1 = __ldg(yp + ba0 + SS);
        uint2 p2 = __ldg(yp + ba0 + 2 * SS);
        uint2 p3 = __ldg(yp + ba0 + 3 * SS);
        float c00 = nm0 * __ldg(&wc[rl0 * 4 + 0]), c01 = nm0 * __ldg(&wc[rl0 * 4 + 1]);
        float c02 = nm0 * __ldg(&wc[rl0 * 4 + 2]), c03 = nm0 * __ldg(&wc[rl0 * 4 + 3]);
        float2 pa0 = __half22float2(*(const __half2*)&p0.x), pb0 = __half22float2(*(const __half2*)&p0.y);
        float2 pa1 = __half22float2(*(const __half2*)&p1.x), pb1 = __half22float2(*(const __half2*)&p1.y);
        float2 pa2 = __half22float2(*(const __half2*)&p2.x), pb2 = __half22float2(*(const __half2*)&p2.y);
        float2 pa3 = __half22float2(*(const __half2*)&p3.x), pb3 = __half22float2(*(const __half2*)&p3.y);
        acc.x += c00 * pa0.x + c01 * pa1.x + c02 * pa2.x + c03 * pa3.x;
        acc.y += c00 * pa0.y + c01 * pa1.y + c02 * pa2.y + c03 * pa3.y;
        acc.z += c00 * pb0.x + c01 * pb1.x + c02 * pb2.x + c03 * pb3.x;
        acc.w += c00 * pb0.y + c01 * pb1.y + c02 * pb2.y + c03 * pb3.y;
    }
    float4* op = (float4*)(out + (long)d * HH) + lane;
    float4 cur = *op;
    cur.x += acc.x; cur.y += acc.y; cur.z += acc.z; cur.w += acc.w;
    *op = cur;
}

// Layer 2: 4 threads/node, T2 gather, 4-edge unrolled.
__global__ void __launch_bounds__(256) agg2_k(
    const int* __restrict__ off, const uint2* __restrict__ rec,
    const __half* __restrict__ T2, float* __restrict__ out) {
    int tid = blockIdx.x * 256 + threadIdx.x;
    int d = tid >> 2;
    if (d >= NN) return;
    int q = tid & 3;
    int beg = __ldg(&off[d]);
    int end = __ldg(&off[d + 1]);
    if (beg == end) return;
    const uint2* tp = (const uint2*)T2;
    float4 acc = {0.f, 0.f, 0.f, 0.f};
    int i = beg;
    for (; i + 3 < end; i += 4) {
        uint2 e0 = __ldg(&rec[i]),     e1 = __ldg(&rec[i + 1]);
        uint2 e2 = __ldg(&rec[i + 2]), e3 = __ldg(&rec[i + 3]);
        size_t r0 = (size_t)(e0.x >> 16) * NN + (e0.x & 0xFFFFu);
        size_t r1 = (size_t)(e1.x >> 16) * NN + (e1.x & 0xFFFFu);
        size_t r2 = (size_t)(e2.x >> 16) * NN + (e2.x & 0xFFFFu);
        size_t r3 = (size_t)(e3.x >> 16) * NN + (e3.x & 0xFFFFu);
        uint2 u0 = __ldg(tp + r0 * 4 + q);
        uint2 u1 = __ldg(tp + r1 * 4 + q);
        uint2 u2 = __ldg(tp + r2 * 4 + q);
        uint2 u3 = __ldg(tp + r3 * 4 + q);
        float n0 = __uint_as_float(e0.y), n1 = __uint_as_float(e1.y);
        float n2 = __uint_as_float(e2.y), n3 = __uint_as_float(e3.y);
        float2 a0 = __half22float2(*(const __half2*)&u0.x), b0 = __half22float2(*(const __half2*)&u0.y);
        float2 a1 = __half22float2(*(const __half2*)&u1.x), b1 = __half22float2(*(const __half2*)&u1.y);
        float2 a2 = __half22float2(*(const __half2*)&u2.x), b2 = __half22float2(*(const __half2*)&u2.y);
        float2 a3 = __half22float2(*(const __half2*)&u3.x), b3 = __half22float2(*(const __half2*)&u3.y);
        acc.x += a0.x * n0 + a1.x * n1 + a2.x * n2 + a3.x * n3;
        acc.y += a0.y * n0 + a1.y * n1 + a2.y * n2 + a3.y * n3;
        acc.z += b0.x * n0 + b1.x * n1 + b2.x * n2 + b3.x * n3;
        acc.w += b0.y * n0 + b1.y * n1 + b2.y * n2 + b3.y * n3;
    }
    for (; i < end; i++) {
        uint2 e0 = __ldg(&rec[i]);
        size_t r0 = (size_t)(e0.x >> 16) * NN + (e0.x & 0xFFFFu);
        uint2 u0 = __ldg(tp + r0 * 4 + q);
        float n0 = __uint_as_float(e0.y);
        float2 a0 = __half22float2(*(const __half2*)&u0.x), b0 = __half22float2(*(const __half2*)&u0.y);
        acc.x += a0.x * n0; acc.y += a0.y * n0;
        acc.z += b0.x * n0; acc.w += b0.y * n0;
    }
    float4* op = (float4*)(out + (long)d * CC) + q;
    float4 cur = *op;
    cur.x += acc.x; cur.y += acc.y; cur.z += acc.z; cur.w += acc.w;
    *op = cur;
}

// ---------------- fp16 HMMA: Y_b = relu(x0) @ B1_b ----------------
__global__ void __launch_bounds__(256, 3) mma_f16(
    const float* __restrict__ X, const __half* __restrict__ Wf,
    __half* __restrict__ Yh) {
    extern __shared__ char sm[];
    const int tid = threadIdx.x;
    const int w = tid >> 5;
    const int lane = tid & 31;
    const int slice = blockIdx.y;
    const int row0 = blockIdx.x * 64;
    {
        const uint2* g = (const uint2*)(Wf + slice * 16384);
#pragma unroll
        for (int i = 0; i < 16; i++) {
            int r = w * 16 + i;
            uint2 v = __ldg(g + r * 32 + lane);
            *(uint2*)(sm + FW_OFF + r * (LSTRIDE * 2) + lane * 8) = v;
        }
    }
    {
#pragma unroll
        for (int i = 0; i < 8; i++) {
            int r = w * 8 + i;
            int rg = row0 + r;
            float4 q = (rg < NN) ? __ldg((const float4*)X + (long)rg * 32 + lane)
                                 : make_float4(0.f, 0.f, 0.f, 0.f);
            uint2 u = { pack_f16(fmaxf(q.x, 0.f), fmaxf(q.y, 0.f)),
                        pack_f16(fmaxf(q.z, 0.f), fmaxf(q.w, 0.f)) };
            *(uint2*)(sm + FA_OFF + r * (LSTRIDE * 2) + lane * 8) = u;
        }
    }
    __syncthreads();

    const int wm = w & 1, wn = w >> 1;
    const int r0 = wm * 32, c0 = wn * 32;
    const uint32_t lrow = lane & 15;
    const uint32_t lkh = (lane >> 4) << 3;
    const uint32_t sA = smem_u32(sm + FA_OFF), sW = smem_u32(sm + FW_OFF);

    float acc[2][4][4];
#pragma unroll
    for (int mi = 0; mi < 2; mi++)
#pragma unroll
        for (int j = 0; j < 4; j++)
            acc[mi][j][0] = acc[mi][j][1] = acc[mi][j][2] = acc[mi][j][3] = 0.f;

#pragma unroll
    for (int ks = 0; ks < 8; ks++) {
        const uint32_t kb = ks * 16 + lkh;
        uint32_t A[2][4], B[2][4];
#pragma unroll
        for (int mi = 0; mi < 2; mi++)
            LDSM4(A[mi], sA + ((r0 + mi * 16 + lrow) * LSTRIDE + kb) * 2);
#pragma unroll
        for (int nj = 0; nj < 2; nj++)
            LDSM4(B[nj], sW + ((c0 + nj * 16 + lrow) * LSTRIDE + kb) * 2);
#pragma unroll
        for (int mi = 0; mi < 2; mi++)
#pragma unroll
            for (int nj = 0; nj < 2; nj++) {
                MMA16816F(acc[mi][nj * 2],     A[mi][0], A[mi][1], A[mi][2], A[mi][3], B[nj][0], B[nj][2]);
                MMA16816F(acc[mi][nj * 2 + 1], A[mi][0], A[mi][1], A[mi][2], A[mi][3], B[nj][1], B[nj][3]);
            }
    }

    __half* O = Yh + (size_t)slice * NN * HH;
    const int g = lane >> 2, tg = lane & 3;
#pragma unroll
    for (int mi = 0; mi < 2; mi++) {
        long ra = row0 + r0 + mi * 16 + g;
        long rb = ra + 8;
#pragma unroll
        for (int j = 0; j < 4; j++) {
            int col = c0 + j * 8 + tg * 2;
            if (ra < NN) *(uint32_t*)(O + ra * 128 + col) = pack_f16(acc[mi][j][0], acc[mi][j][1]);
            if (rb < NN) *(uint32_t*)(O + rb * 128 + col) = pack_f16(acc[mi][j][2], acc[mi][j][3]);
        }
    }
}

// ---------------- bf16 hi/lo HMMA: x1 = relu(x0) @ loop1 + bias1 ----------------
__global__ void __launch_bounds__(256, 2) mma_x1(
    const float* __restrict__ X,
    const __nv_bfloat16* __restrict__ Wth, const __nv_bfloat16* __restrict__ Wtl,
    float* __restrict__ x1, const float* __restrict__ bias1) {
    extern __shared__ char sm[];
    const int tid = threadIdx.x;
    const int w = tid >> 5;
    const int lane = tid & 31;
    const int row0 = blockIdx.x * 64;
    {
        const uint2* gh = (const uint2*)(Wth + 4 * 16384);
        const uint2* gl = (const uint2*)(Wtl + 4 * 16384);
#pragma unroll
        for (int i = 0; i < 16; i++) {
            int r = w * 16 + i;
            uint2 vh = __ldg(gh + r * 32 + lane);
            uint2 vl = __ldg(gl + r * 32 + lane);
            *(uint2*)(sm + WH_OFF + r * (LSTRIDE * 2) + lane * 8) = vh;
            *(uint2*)(sm + WL_OFF + r * (LSTRIDE * 2) + lane * 8) = vl;
        }
    }
    {
#pragma unroll
        for (int i = 0; i < 8; i++) {
            int r = w * 8 + i;
            int rg = row0 + r;
            float4 q = (rg < NN) ? __ldg((const float4*)X + (long)rg * 32 + lane)
                                 : make_float4(0.f, 0.f, 0.f, 0.f);
            q.x = fmaxf(q.x, 0.f); q.y = fmaxf(q.y, 0.f);
            q.z = fmaxf(q.z, 0.f); q.w = fmaxf(q.w, 0.f);
            float hx = __bfloat162float(__float2bfloat16(q.x));
            float hy = __bfloat162float(__float2bfloat16(q.y));
            float hz = __bfloat162float(__float2bfloat16(q.z));
            float hw = __bfloat162float(__float2bfloat16(q.w));
            uint2 uh = { pack_bf16(q.x, q.y), pack_bf16(q.z, q.w) };
            uint2 ul = { pack_bf16(q.x - hx, q.y - hy), pack_bf16(q.z - hz, q.w - hw) };
            *(uint2*)(sm + AH_OFF + r * (LSTRIDE * 2) + lane * 8) = uh;
            *(uint2*)(sm + AL_OFF + r * (LSTRIDE * 2) + lane * 8) = ul;
        }
    }
    __syncthreads();

    const int wm = w & 1, wn = w >> 1;
    const int r0 = wm * 32, c0 = wn * 32;
    const uint32_t lrow = lane & 15;
    const uint32_t lkh = (lane >> 4) << 3;
    const uint32_t sAH = smem_u32(sm + AH_OFF), sAL = smem_u32(sm + AL_OFF);
    const uint32_t sWH = smem_u32(sm + WH_OFF), sWL = smem_u32(sm + WL_OFF);

    float acc[2][4][4];
#pragma unroll
    for (int mi = 0; mi < 2; mi++)
#pragma unroll
        for (int j = 0; j < 4; j++)
            acc[mi][j][0] = acc[mi][j][1] = acc[mi][j][2] = acc[mi][j][3] = 0.f;

#pragma unroll
    for (int ks = 0; ks < 8; ks++) {
        const uint32_t kb = ks * 16 + lkh;
        uint32_t AH[2][4], AL[2][4], BH[2][4], BL[2][4];
#pragma unroll
        for (int mi = 0; mi < 2; mi++) {
            uint32_t off = ((r0 + mi * 16 + lrow) * LSTRIDE + kb) * 2;
            LDSM4(AH[mi], sAH + off);
            LDSM4(AL[mi], sAL + off);
        }
#pragma unroll
        for (int nj = 0; nj < 2; nj++) {
            uint32_t off = ((c0 + nj * 16 + lrow) * LSTRIDE + kb) * 2;
            LDSM4(BH[nj], sWH + off);
            LDSM4(BL[nj], sWL + off);
        }
#pragma unroll
        for (int mi = 0; mi < 2; mi++)
#pragma unroll
            for (int nj = 0; nj < 2; nj++) {
                float* cA = acc[mi][nj * 2];
                float* cB = acc[mi][nj * 2 + 1];
                MMA16816BF(cA, AH[mi][0], AH[mi][1], AH[mi][2], AH[mi][3], BH[nj][0], BH[nj][2]);
                MMA16816BF(cA, AH[mi][0], AH[mi][1], AH[mi][2], AH[mi][3], BL[nj][0], BL[nj][2]);
                MMA16816BF(cA, AL[mi][0], AL[mi][1], AL[mi][2], AL[mi][3], BH[nj][0], BH[nj][2]);
                MMA16816BF(cB, AH[mi][0], AH[mi][1], AH[mi][2], AH[mi][3], BH[nj][1], BH[nj][3]);
                MMA16816BF(cB, AH[mi][0], AH[mi][1], AH[mi][2], AH[mi][3], BL[nj][1], BL[nj][3]);
                MMA16816BF(cB, AL[mi][0], AL[mi][1], AL[mi][2], AL[mi][3], BH[nj][1], BH[nj][3]);
            }
    }

    const int g = lane >> 2, tg = lane & 3;
#pragma unroll
    for (int mi = 0; mi < 2; mi++) {
        long ra = row0 + r0 + mi * 16 + g;
        long rb = ra + 8;
#pragma unroll
        for (int j = 0; j < 4; j++) {
            int col = c0 + j * 8 + tg * 2;
            float b0 = __ldg(&bias1[col]), b1 = __ldg(&bias1[col + 1]);
            if (ra < NN) {
                float2 v = { acc[mi][j][0] + b0, acc[mi][j][1] + b1 };
                *(float2*)(x1 + ra * 128 + col) = v;
            }
            if (rb < NN) {
                float2 v = { acc[mi][j][2] + b0, acc[mi][j][3] + b1 };
                *(float2*)(x1 + rb * 128 + col) = v;
            }
        }
    }
}

// ---------------- layer 2 transform, F=16; mode 0: bases->Z (grid.y=4), mode 1: loop->out+bias ----------------
__global__ void __launch_bounds__(128) transform16(
    const float* __restrict__ X, const float* __restrict__ bases2,
    const float* __restrict__ loop2, const float* __restrict__ bias2,
    float* __restrict__ Z, float* __restrict__ out, int mode) {
    __shared__ float ws[128 * 16];
    __shared__ float xs[64][129];
    const int y = blockIdx.y;
    const float* W = (mode == 0) ? (bases2 + y * 2048) : loop2;
    float* O = (mode == 0) ? (Z + (long)y * NN * CC) : out;
    const int t = threadIdx.x;
    const int col = t & 15, rg = t >> 4;
    const int row0 = blockIdx.x * 64;
    for (int i = t; i < 128 * 16; i += 128) ws[i] = __ldg(&W[i]);
#pragma unroll 4
    for (int i = 0; i < 64; i++) {
        int rr = row0 + i;
        float v = (rr < NN) ? __ldg(&X[(long)rr * 128 + t]) : 0.f;
        xs[i][t] = fmaxf(v, 0.f);
    }
    __syncthreads();
    const float bv = (mode == 1) ? __ldg(&bias2[col]) : 0.f;
    for (int p = 0; p < 8; p++) {
        int rl = p * 8 + rg;
        float a = 0.f;
#pragma unroll 16
        for (int d = 0; d < 128; d++) a = fmaf(xs[rl][d], ws[d * 16 + col], a);
        int rr = row0 + rl;
        if (rr < NN) O[(long)rr * 16 + col] = a + bv;
    }
}

// ---------------- launch ----------------
extern "C" void kernel_launch(void* const* d_in, const int* in_sizes, int n_in,
                              void* d_out, int out_size) {
    const int*   src    = (const int*)d_in[0];
    const int*   dst    = (const int*)d_in[1];
    const int*   h      = (const int*)d_in[2];
    const int*   rtab   = (const int*)d_in[3];
    const float* norm   = (const float*)d_in[4];
    const float* bases0 = (const float*)d_in[5];
    const float* wcomp0 = (const float*)d_in[6];
    const float* loop0  = (const float*)d_in[7];
    const float* bias0  = (const float*)d_in[8];
    const float* bases1 = (const float*)d_in[9];
    const float* wcomp1 = (const float*)d_in[10];
    const float* loop1  = (const float*)d_in[11];
    const float* bias1  = (const float*)d_in[12];
    const float* bases2 = (const float*)d_in[13];
    const float* wcomp2 = (const float*)d_in[14];
    const float* loop2  = (const float*)d_in[15];
    const float* bias2  = (const float*)d_in[16];
    float* out = (float*)d_out;

    float *p_x0, *p_x1, *p_z2;
    __half *p_t0, *p_t2, *p_y1h, *p_wf;
    __nv_bfloat16 *p_whi, *p_wlo;
    int *p_deg, *p_cur, *p_off;
    uint2 *p_rec;
    cudaGetSymbolAddress((void**)&p_x0, g_x0);
    cudaGetSymbolAddress((void**)&p_x1, g_x1);
    cudaGetSymbolAddress((void**)&p_t0, g_t0);
    cudaGetSymbolAddress((void**)&p_t2, g_t2);
    cudaGetSymbolAddress((void**)&p_y1h, g_y1h);
    cudaGetSymbolAddress((void**)&p_z2, g_z2);
    cudaGetSymbolAddress((void**)&p_whi, g_w1thi);
    cudaGetSymbolAddress((void**)&p_wlo, g_w1tlo);
    cudaGetSymbolAddress((void**)&p_wf, g_w1tf);
    cudaGetSymbolAddress((void**)&p_deg, g_deg);
    cudaGetSymbolAddress((void**)&p_cur, g_cur);
    cudaGetSymbolAddress((void**)&p_off, g_off);
    cudaGetSymbolAddress((void**)&p_rec, g_rec);

    static int init_done = 0;
    static cudaStream_t s1, s2;
    static cudaEvent_t evRoot, evCmp0, evPrep, evAgg0, evX1, evAgg1, evT16b, evEnd;
    if (!init_done) {
        cudaFuncSetAttribute(mma_x1, cudaFuncAttributeMaxDynamicSharedMemorySize, SMEM_X1);
        cudaFuncSetAttribute(mma_f16, cudaFuncAttributeMaxDynamicSharedMemorySize, SMEM_F16);
        cudaStreamCreateWithFlags(&s1, cudaStreamNonBlocking);
        cudaStreamCreateWithFlags(&s2, cudaStreamNonBlocking);
        cudaEventCreateWithFlags(&evRoot, cudaEventDisableTiming);
        cudaEventCreateWithFlags(&evCmp0, cudaEventDisableTiming);
        cudaEventCreateWithFlags(&evPrep, cudaEventDisableTiming);
        cudaEventCreateWithFlags(&evAgg0, cudaEventDisableTiming);
        cudaEventCreateWithFlags(&evX1, cudaEventDisableTiming);
        cudaEventCreateWithFlags(&evAgg1, cudaEventDisableTiming);
        cudaEventCreateWithFlags(&evT16b, cudaEventDisableTiming);
        cudaEventCreateWithFlags(&evEnd, cudaEventDisableTiming);
        init_done = 1;
    }

    const int e_blocks  = (EE + 255) / 256;
    const int row_t64   = (NN + 63) / 64;
    const int ncvt      = (NN * 32 + 255) / 256;
    const int agg_blocks = (NN + 7) / 8;

    cudaEventRecord(evRoot, 0);
    cudaStreamWaitEvent(s1, evRoot, 0);
    cudaStreamWaitEvent(s2, evRoot, 0);

    // s2: compose0, then weight images
    compose0_k<<<ncvt, 256, 0, s2>>>(bases0, wcomp0, p_t0);
    cudaEventRecord(evCmp0, s2);
    prep_w1t<<<(5 * 16384 + 255) / 256, 256, 0, s2>>>(bases1, loop1, p_whi, p_wlo, p_wf);
    cudaEventRecord(evPrep, s2);

    // s1: CSR chain (memset nodes replace zero_k)
    cudaMemsetAsync(p_deg, 0, NN * sizeof(int), s1);
    cudaMemsetAsync(p_cur, 0, NN * sizeof(int), s1);
    hist_k<<<e_blocks, 256, 0, s1>>>(dst, p_deg);
    scan_k<<<1, 1024, 0, s1>>>(p_deg, p_off);
    fill_k<<<e_blocks, 256, 0, s1>>>(src, dst, rtab, norm, p_off, p_cur, p_rec);

    // s1: layer-0 aggregate (fused init; resolves h[] inline)
    cudaStreamWaitEvent(s1, evCmp0, 0);
    aggT_k<<<agg_blocks, 256, 0, s1>>>(p_off, p_rec, h, loop0, bias0, p_t0, p_x0);
    cudaEventRecord(evAgg0, s1);

    // s2: self-loop GEMM
    cudaStreamWaitEvent(s2, evAgg0, 0);
    mma_x1<<<row_t64, 256, SMEM_X1, s2>>>(p_x0, p_whi, p_wlo, p_x1, bias1);
    cudaEventRecord(evX1, s2);

    // s1: basis GEMMs, then 4-basis L2-resident aggregate
    cudaStreamWaitEvent(s1, evPrep, 0);
    mma_f16<<<dim3(row_t64, 4), 256, SMEM_F16, s1>>>(p_x0, p_wf, p_y1h);
    cudaStreamWaitEvent(s1, evX1, 0);
    aggY_k<<<agg_blocks, 256, 0, s1>>>(p_off, p_rec, wcomp1, p_y1h, p_x1);
    cudaEventRecord(evAgg1, s1);

    // s2: layer-2 self-loop -> out
    cudaStreamWaitEvent(s2, evAgg1, 0);
    transform16<<<dim3(row_t64, 1), 128, 0, s2>>>(p_x1, bases2, loop2, bias2, p_z2, out, 1);
    cudaEventRecord(evT16b, s2);

    // s1: layer-2 basis path
    transform16<<<dim3(row_t64, 4), 128, 0, s1>>>(p_x1, bases2, loop2, bias2, p_z2, out, 0);
    compose2_k<<<(NN * 4 + 255) / 256, 256, 0, s1>>>(p_z2, wcomp2, p_t2);
    cudaStreamWaitEvent(s1, evT16b, 0);
    agg2_k<<<(NN * 4 + 255) / 256, 256, 0, s1>>>(p_off, p_rec, p_t2, out);
    cudaEventRecord(evEnd, s1);

    cudaStreamWaitEvent(0, evEnd, 0);
}